// round 1
// baseline (speedup 1.0000x reference)
#include <cuda_runtime.h>
#include <math.h>

#define BB   2
#define SS   2048
#define DD   2048
#define HH   16
#define HKVN 4
#define GGN  4
#define HDN  128
#define MROWS (BB*SS)
#define KVD  (HKVN*HDN)   // 512

// ---------------- scratch (device globals; no cudaMalloc allowed) ----------
__device__ float g_q[MROWS*DD];        // q_flat  [4096, 2048]
__device__ float g_k[MROWS*KVD];       // k_flat  [4096, 512]
__device__ float g_v[MROWS*KVD];       // v_flat  [4096, 512]
__device__ float g_bias[BB*HKVN*SS];   // bias    [b, n, s]
__device__ float g_vmean[BB*HKVN*HDN]; // mean over s of v  [b, n, d]
__device__ float g_o[MROWS*DD];        // attention output, [4096, 2048]

// ---------------- generic tiled fp32 GEMM: C[M,N] = A[M,K] @ B[K,N] --------
// 64x64 block tile, K-tile 32, 256 threads, 4x4 per-thread microtile.
__global__ void gemm64(const float* __restrict__ A, const float* __restrict__ B,
                       float* __restrict__ C, int M, int N, int K) {
    __shared__ float As[32][68];   // A stored transposed: As[k][m]
    __shared__ float Bs[32][68];   // Bs[k][n]
    const int tx = threadIdx.x & 15;
    const int ty = threadIdx.x >> 4;
    const int m0 = blockIdx.y << 6;
    const int n0 = blockIdx.x << 6;

    float acc[4][4];
    #pragma unroll
    for (int i = 0; i < 4; i++)
        #pragma unroll
        for (int j = 0; j < 4; j++) acc[i][j] = 0.f;

    for (int k0 = 0; k0 < K; k0 += 32) {
        #pragma unroll
        for (int i = 0; i < 8; i++) {
            int idx = threadIdx.x + i * 256;       // 2048 elems of A tile
            int r = idx >> 5, c = idx & 31;
            As[c][r] = A[(m0 + r) * K + k0 + c];
        }
        #pragma unroll
        for (int i = 0; i < 8; i++) {
            int idx = threadIdx.x + i * 256;       // 2048 elems of B tile
            int kk = idx >> 6, j = idx & 63;
            Bs[kk][j] = B[(k0 + kk) * N + n0 + j];
        }
        __syncthreads();
        #pragma unroll
        for (int kk = 0; kk < 32; kk++) {
            float4 a4 = *(const float4*)&As[kk][ty << 2];
            float4 b4 = *(const float4*)&Bs[kk][tx << 2];
            float a[4] = {a4.x, a4.y, a4.z, a4.w};
            float b[4] = {b4.x, b4.y, b4.z, b4.w};
            #pragma unroll
            for (int i = 0; i < 4; i++)
                #pragma unroll
                for (int j = 0; j < 4; j++)
                    acc[i][j] += a[i] * b[j];
        }
        __syncthreads();
    }
    #pragma unroll
    for (int i = 0; i < 4; i++) {
        float4 o = make_float4(acc[i][0], acc[i][1], acc[i][2], acc[i][3]);
        *(float4*)&C[(m0 + (ty << 2) + i) * N + n0 + (tx << 2)] = o;
    }
}

// ---------------- bias: sigmoid(q_flat @ Wg) * (v_flat @ Wd) ---------------
// one warp per (row, n)
__global__ void bias_kernel(const float* __restrict__ Wg, const float* __restrict__ Wd) {
    int gwarp = (blockIdx.x * blockDim.x + threadIdx.x) >> 5;
    int lane  = threadIdx.x & 31;
    if (gwarp >= MROWS * HKVN) return;
    int n   = gwarp & 3;
    int row = gwarp >> 2;

    const float* qr = g_q + (size_t)row * DD;
    const float* vr = g_v + (size_t)row * KVD;
    float sg = 0.f, sd = 0.f;
    for (int d = lane; d < DD;  d += 32) sg += qr[d] * Wg[d * HKVN + n];
    for (int d = lane; d < KVD; d += 32) sd += vr[d] * Wd[d * HKVN + n];
    #pragma unroll
    for (int off = 16; off; off >>= 1) {
        sg += __shfl_xor_sync(0xffffffffu, sg, off);
        sd += __shfl_xor_sync(0xffffffffu, sd, off);
    }
    if (lane == 0) {
        float bias = sd / (1.f + expf(-sg));   // sigmoid(gate)*delta
        int b = row / SS, s = row % SS;
        g_bias[(b * HKVN + n) * SS + s] = bias;
    }
}

// ---------------- vmean[b,n,d] = mean over s of v ---------------------------
__global__ void vmean_kernel() {
    int bn = blockIdx.x;           // 0..7
    int d  = threadIdx.x;          // 0..127
    int b = bn >> 2, n = bn & 3;
    float s = 0.f;
    for (int t = 0; t < SS; t++)
        s += g_v[((size_t)(b * SS + t)) * KVD + n * HDN + d];
    g_vmean[bn * HDN + d] = s * (1.f / SS);
}

// ---------------- flash attention with dynamic mask ------------------------
// grid: (S/32, H, B); block 256 (8 warps x 4 queries); lane owns key within
// tile for scores and 4 head-dims for the output accumulator.
__global__ void attn_kernel() {
    extern __shared__ float sm[];
    float* q_sh = sm;                 // 32 x 132 (padded)
    float* k_sh = sm + 32 * 132;
    float* v_sh = sm + 2 * 32 * 132;

    const int qtile = blockIdx.x;
    const int h     = blockIdx.y;
    const int b     = blockIdx.z;
    const int n     = h >> 2;                 // kv head
    const int q0    = qtile << 5;
    const int tid   = threadIdx.x;
    const int w     = tid >> 5;
    const int lane  = tid & 31;
    const int d0    = lane << 2;
    const int qrb   = w << 2;                 // warp's first query within tile
    const float scale = 0.0883883476483184f;  // 128^-0.5

    // load Q tile
    #pragma unroll
    for (int i = 0; i < 16; i++) {
        int idx = tid + i * 256;
        int r = idx >> 7, d = idx & 127;
        q_sh[r * 132 + d] = g_q[((size_t)(b * SS + q0 + r)) * DD + h * HDN + d];
    }

    float m[4], l[4], o[4][4];
    #pragma unroll
    for (int qi = 0; qi < 4; qi++) {
        m[qi] = -INFINITY; l[qi] = 0.f;
        #pragma unroll
        for (int j = 0; j < 4; j++) o[qi][j] = 0.f;
    }

    for (int kt = 0; kt <= qtile; kt++) {
        const int kbase = kt << 5;
        __syncthreads();
        #pragma unroll
        for (int i = 0; i < 16; i++) {
            int idx = tid + i * 256;
            int r = idx >> 7, d = idx & 127;
            size_t src = ((size_t)(b * SS + kbase + r)) * KVD + n * HDN + d;
            k_sh[r * 132 + d] = g_k[src];
            v_sh[r * 132 + d] = g_v[src];
        }
        __syncthreads();

        const int   key = kbase + lane;
        const float bk  = g_bias[(b * HKVN + n) * SS + key];

        // scores: lane computes dot(q_row, k[key]) for its 4 query rows
        float s4[4] = {0.f, 0.f, 0.f, 0.f};
        const float4* kp = (const float4*)(k_sh + lane * 132);
        #pragma unroll 8
        for (int c = 0; c < 32; c++) {
            float4 kv = kp[c];
            #pragma unroll
            for (int qi = 0; qi < 4; qi++) {
                float4 qv = ((const float4*)(q_sh + (qrb + qi) * 132))[c];
                s4[qi] += qv.x * kv.x + qv.y * kv.y + qv.z * kv.z + qv.w * kv.w;
            }
        }

        #pragma unroll
        for (int qi = 0; qi < 4; qi++) {
            const int q = q0 + qrb + qi;
            const bool allowed = (key <= q) && (bk > 0.f);
            float logit = allowed ? (s4[qi] * scale + bk) : -INFINITY;

            float tmax = logit;
            #pragma unroll
            for (int off = 16; off; off >>= 1)
                tmax = fmaxf(tmax, __shfl_xor_sync(0xffffffffu, tmax, off));
            float mnew = fmaxf(m[qi], tmax);
            if (mnew == -INFINITY) continue;   // warp-uniform: no key allowed yet

            float corr = (m[qi] == -INFINITY) ? 0.f : __expf(m[qi] - mnew);
            float p    = allowed ? __expf(logit - mnew) : 0.f;
            float psum = p;
            #pragma unroll
            for (int off = 16; off; off >>= 1)
                psum += __shfl_xor_sync(0xffffffffu, psum, off);
            l[qi] = l[qi] * corr + psum;
            m[qi] = mnew;
            #pragma unroll
            for (int j = 0; j < 4; j++) o[qi][j] *= corr;

            #pragma unroll 8
            for (int k2 = 0; k2 < 32; k2++) {
                float pk = __shfl_sync(0xffffffffu, p, k2);
                if (pk != 0.f) {
                    float4 vv = *(const float4*)(v_sh + k2 * 132 + d0);
                    o[qi][0] += pk * vv.x; o[qi][1] += pk * vv.y;
                    o[qi][2] += pk * vv.z; o[qi][3] += pk * vv.w;
                }
            }
        }
    }

    // epilogue: normalize, or all-masked fallback (uniform softmax over ALL
    // keys => mean of v, matching reference finfo.min semantics)
    #pragma unroll
    for (int qi = 0; qi < 4; qi++) {
        const int q = q0 + qrb + qi;
        float4 res;
        if (l[qi] > 0.f) {
            float inv = 1.f / l[qi];
            res = make_float4(o[qi][0] * inv, o[qi][1] * inv,
                              o[qi][2] * inv, o[qi][3] * inv);
        } else {
            res = *(const float4*)(g_vmean + (b * HKVN + n) * HDN + d0);
        }
        *(float4*)(g_o + ((size_t)(b * SS + q)) * DD + h * HDN + d0) = res;
    }
}

// ---------------- launch -----------------------------------------------------
extern "C" void kernel_launch(void* const* d_in, const int* in_sizes, int n_in,
                              void* d_out, int out_size) {
    const float* X  = (const float*)d_in[0];
    const float* Wq = (const float*)d_in[1];
    const float* Wk = (const float*)d_in[2];
    const float* Wv = (const float*)d_in[3];
    const float* Wg = (const float*)d_in[4];
    const float* Wd = (const float*)d_in[5];
    const float* Wo = (const float*)d_in[6];
    float* out = (float*)d_out;

    float *qp, *kp, *vp, *op;
    cudaGetSymbolAddress((void**)&qp, g_q);
    cudaGetSymbolAddress((void**)&kp, g_k);
    cudaGetSymbolAddress((void**)&vp, g_v);
    cudaGetSymbolAddress((void**)&op, g_o);

    const int smem = 3 * 32 * 132 * 4;  // 50688 B
    cudaFuncSetAttribute(attn_kernel, cudaFuncAttributeMaxDynamicSharedMemorySize, smem);

    // projections
    gemm64<<<dim3(DD / 64, MROWS / 64), 256>>>(X, Wq, qp, MROWS, DD,  DD);
    gemm64<<<dim3(KVD / 64, MROWS / 64), 256>>>(X, Wk, kp, MROWS, KVD, DD);
    gemm64<<<dim3(KVD / 64, MROWS / 64), 256>>>(X, Wv, vp, MROWS, KVD, DD);

    // dynamic mask bias + all-masked fallback
    bias_kernel<<<(MROWS * HKVN * 32) / 256, 256>>>(Wg, Wd);
    vmean_kernel<<<BB * HKVN, HDN>>>();

    // attention
    attn_kernel<<<dim3(SS / 32, HH, BB), 256, smem>>>();

    // output projection
    gemm64<<<dim3(DD / 64, MROWS / 64), 256>>>(op, Wo, out, MROWS, DD, DD);
}

// round 3
// speedup vs baseline: 1.2149x; 1.2149x over previous
#include <cuda_runtime.h>
#include <math.h>
#include <stdint.h>

#define BB   2
#define SS   2048
#define DD   2048
#define HH   16
#define HKVN 4
#define GGN  4
#define HDN  128
#define MROWS (BB*SS)
#define KVD  (HKVN*HDN)   // 512

// ---------------- scratch (device globals; no cudaMalloc allowed) ----------
__device__ float g_q[MROWS*DD];
__device__ float g_k[MROWS*KVD];
__device__ float g_v[MROWS*KVD];
__device__ float g_bias[BB*HKVN*SS];
__device__ float g_vmean[BB*HKVN*HDN];
__device__ float g_o[MROWS*DD];

// ---------------- 3xTF32 tensor-core GEMM: C = A @ B -----------------------
// 128x128 CTA tile, BK=32, 8 warps (32x64 each), cp.async double buffer.
// Each operand split a = hi + lo (two rna roundings); accumulate
// Ahi*Bhi + Ahi*Blo + Alo*Bhi  -> ~fp32 precision on tensor pipe.

#define ASTR 36
#define BSTR 136
#define A_TILE (128*ASTR)
#define B_TILE (32*BSTR)
#define GEMM_SMEM ((2*A_TILE + 2*B_TILE)*4)   // 71680 bytes

__device__ __forceinline__ void split_tf32(float f, uint32_t& hi, uint32_t& lo) {
    uint32_t h;
    asm("cvt.rna.tf32.f32 %0, %1;" : "=r"(h) : "f"(f));
    float r = f - __uint_as_float(h);          // exact residual (low 13 bits)
    asm("cvt.rna.tf32.f32 %0, %1;" : "=r"(lo) : "f"(r));
    hi = h;
}

__device__ __forceinline__ void mma_tf32(float* c, const uint32_t* a, const uint32_t* b) {
    asm volatile(
        "mma.sync.aligned.m16n8k8.row.col.f32.tf32.tf32.f32 "
        "{%0,%1,%2,%3},{%4,%5,%6,%7},{%8,%9},{%0,%1,%2,%3};"
        : "+f"(c[0]), "+f"(c[1]), "+f"(c[2]), "+f"(c[3])
        : "r"(a[0]), "r"(a[1]), "r"(a[2]), "r"(a[3]), "r"(b[0]), "r"(b[1]));
}

#define CP16(dst, src) asm volatile("cp.async.cg.shared.global [%0], [%1], 16;" :: "r"(dst), "l"(src))

__global__ __launch_bounds__(256, 2) void gemm_tf32x3(const float* __restrict__ A,
                                                      const float* __restrict__ B,
                                                      float* __restrict__ C,
                                                      int M, int N, int K) {
    extern __shared__ float sm[];
    float* As = sm;
    float* Bs = sm + 2 * A_TILE;

    const int tid  = threadIdx.x;
    const int wid  = tid >> 5;
    const int lane = tid & 31;
    const int wm   = (wid & 3) << 5;
    const int wn   = (wid >> 2) << 6;
    const int m0   = blockIdx.y << 7;
    const int n0   = blockIdx.x << 7;
    const int lr   = lane >> 2;
    const int lc   = lane & 3;

    float acc[2][8][4];
    #pragma unroll
    for (int mt = 0; mt < 2; mt++)
        #pragma unroll
        for (int nt = 0; nt < 8; nt++)
            #pragma unroll
            for (int i = 0; i < 4; i++) acc[mt][nt][i] = 0.f;

    const int KT = K >> 5;

    auto load_stage = [&](int kt, int s) {
        float* as = As + s * A_TILE;
        float* bs = Bs + s * B_TILE;
        #pragma unroll
        for (int p = 0; p < 4; p++) {
            int idx = tid + (p << 8);
            int r = idx >> 3, kv = (idx & 7) << 2;
            uint32_t dst = (uint32_t)__cvta_generic_to_shared(as + r * ASTR + kv);
            CP16(dst, A + (size_t)(m0 + r) * K + (kt << 5) + kv);
        }
        #pragma unroll
        for (int p = 0; p < 4; p++) {
            int idx = tid + (p << 8);
            int r = idx >> 5, nv = (idx & 31) << 2;
            uint32_t dst = (uint32_t)__cvta_generic_to_shared(bs + r * BSTR + nv);
            CP16(dst, B + (size_t)((kt << 5) + r) * N + n0 + nv);
        }
        asm volatile("cp.async.commit_group;");
    };

    load_stage(0, 0);

    for (int kt = 0; kt < KT; kt++) {
        asm volatile("cp.async.wait_group 0;");
        __syncthreads();
        if (kt + 1 < KT) load_stage(kt + 1, (kt + 1) & 1);

        const float* as = As + (kt & 1) * A_TILE;
        const float* bs = Bs + (kt & 1) * B_TILE;

        #pragma unroll
        for (int ks = 0; ks < 4; ks++) {
            const int kk = ks << 3;
            uint32_t ah[2][4], al[2][4];
            #pragma unroll
            for (int mt = 0; mt < 2; mt++) {
                const float* ap = as + (wm + (mt << 4) + lr) * ASTR + kk + lc;
                split_tf32(ap[0],            ah[mt][0], al[mt][0]);
                split_tf32(ap[8 * ASTR],     ah[mt][1], al[mt][1]);
                split_tf32(ap[4],            ah[mt][2], al[mt][2]);
                split_tf32(ap[8 * ASTR + 4], ah[mt][3], al[mt][3]);
            }
            #pragma unroll
            for (int nt = 0; nt < 8; nt++) {
                const float* bp = bs + (kk + lc) * BSTR + wn + (nt << 3) + lr;
                uint32_t bh[2], bl[2];
                split_tf32(bp[0],        bh[0], bl[0]);
                split_tf32(bp[4 * BSTR], bh[1], bl[1]);
                #pragma unroll
                for (int mt = 0; mt < 2; mt++) {
                    mma_tf32(acc[mt][nt], ah[mt], bh);   // hi*hi
                    mma_tf32(acc[mt][nt], ah[mt], bl);   // hi*lo
                    mma_tf32(acc[mt][nt], al[mt], bh);   // lo*hi
                }
            }
        }
        __syncthreads();
    }

    #pragma unroll
    for (int mt = 0; mt < 2; mt++) {
        #pragma unroll
        for (int nt = 0; nt < 8; nt++) {
            int row = m0 + wm + (mt << 4) + lr;
            int col = n0 + wn + (nt << 3) + (lc << 1);
            *(float2*)&C[(size_t)row * N + col] =
                make_float2(acc[mt][nt][0], acc[mt][nt][1]);
            *(float2*)&C[(size_t)(row + 8) * N + col] =
                make_float2(acc[mt][nt][2], acc[mt][nt][3]);
        }
    }
}

// ---------------- bias: sigmoid(q_flat @ Wg) * (v_flat @ Wd) ---------------
__global__ void bias_kernel(const float* __restrict__ Wg, const float* __restrict__ Wd) {
    int gwarp = (blockIdx.x * blockDim.x + threadIdx.x) >> 5;
    int lane  = threadIdx.x & 31;
    if (gwarp >= MROWS * HKVN) return;
    int n   = gwarp & 3;
    int row = gwarp >> 2;

    const float* qr = g_q + (size_t)row * DD;
    const float* vr = g_v + (size_t)row * KVD;
    float sg = 0.f, sd = 0.f;
    for (int d = lane; d < DD;  d += 32) sg += qr[d] * Wg[d * HKVN + n];
    for (int d = lane; d < KVD; d += 32) sd += vr[d] * Wd[d * HKVN + n];
    #pragma unroll
    for (int off = 16; off; off >>= 1) {
        sg += __shfl_xor_sync(0xffffffffu, sg, off);
        sd += __shfl_xor_sync(0xffffffffu, sd, off);
    }
    if (lane == 0) {
        float bias = sd / (1.f + expf(-sg));
        int b = row / SS, s = row % SS;
        g_bias[(b * HKVN + n) * SS + s] = bias;
    }
}

// ---------------- vmean[b,n,d] = mean over s of v ---------------------------
__global__ void vmean_kernel() {
    int bn = blockIdx.x;
    int d  = threadIdx.x;
    int b = bn >> 2, n = bn & 3;
    float s = 0.f;
    for (int t = 0; t < SS; t++)
        s += g_v[((size_t)(b * SS + t)) * KVD + n * HDN + d];
    g_vmean[bn * HDN + d] = s * (1.f / SS);
}

// ---------------- flash attention with dynamic mask ------------------------
__global__ void attn_kernel() {
    extern __shared__ float smattn[];
    float* q_sh = smattn;
    float* k_sh = smattn + 32 * 132;
    float* v_sh = smattn + 2 * 32 * 132;

    const int qtile = blockIdx.x;
    const int h     = blockIdx.y;
    const int b     = blockIdx.z;
    const int n     = h >> 2;
    const int q0    = qtile << 5;
    const int tid   = threadIdx.x;
    const int w     = tid >> 5;
    const int lane  = tid & 31;
    const int d0    = lane << 2;
    const int qrb   = w << 2;
    const float scale = 0.0883883476483184f;

    #pragma unroll
    for (int i = 0; i < 16; i++) {
        int idx = tid + i * 256;
        int r = idx >> 7, d = idx & 127;
        q_sh[r * 132 + d] = g_q[((size_t)(b * SS + q0 + r)) * DD + h * HDN + d];
    }

    float m[4], l[4], o[4][4];
    #pragma unroll
    for (int qi = 0; qi < 4; qi++) {
        m[qi] = -INFINITY; l[qi] = 0.f;
        #pragma unroll
        for (int j = 0; j < 4; j++) o[qi][j] = 0.f;
    }

    for (int kt = 0; kt <= qtile; kt++) {
        const int kbase = kt << 5;
        __syncthreads();
        #pragma unroll
        for (int i = 0; i < 16; i++) {
            int idx = tid + i * 256;
            int r = idx >> 7, d = idx & 127;
            size_t src = ((size_t)(b * SS + kbase + r)) * KVD + n * HDN + d;
            k_sh[r * 132 + d] = g_k[src];
            v_sh[r * 132 + d] = g_v[src];
        }
        __syncthreads();

        const int   key = kbase + lane;
        const float bk  = g_bias[(b * HKVN + n) * SS + key];

        float s4[4] = {0.f, 0.f, 0.f, 0.f};
        const float4* kp = (const float4*)(k_sh + lane * 132);
        #pragma unroll 8
        for (int c = 0; c < 32; c++) {
            float4 kv = kp[c];
            #pragma unroll
            for (int qi = 0; qi < 4; qi++) {
                float4 qv = ((const float4*)(q_sh + (qrb + qi) * 132))[c];
                s4[qi] += qv.x * kv.x + qv.y * kv.y + qv.z * kv.z + qv.w * kv.w;
            }
        }

        #pragma unroll
        for (int qi = 0; qi < 4; qi++) {
            const int q = q0 + qrb + qi;
            const bool allowed = (key <= q) && (bk > 0.f);
            float logit = allowed ? (s4[qi] * scale + bk) : -INFINITY;

            float tmax = logit;
            #pragma unroll
            for (int off = 16; off; off >>= 1)
                tmax = fmaxf(tmax, __shfl_xor_sync(0xffffffffu, tmax, off));
            float mnew = fmaxf(m[qi], tmax);
            if (mnew == -INFINITY) continue;

            float corr = (m[qi] == -INFINITY) ? 0.f : __expf(m[qi] - mnew);
            float p    = allowed ? __expf(logit - mnew) : 0.f;
            float psum = p;
            #pragma unroll
            for (int off = 16; off; off >>= 1)
                psum += __shfl_xor_sync(0xffffffffu, psum, off);
            l[qi] = l[qi] * corr + psum;
            m[qi] = mnew;
            #pragma unroll
            for (int j = 0; j < 4; j++) o[qi][j] *= corr;

            #pragma unroll 8
            for (int k2 = 0; k2 < 32; k2++) {
                float pk = __shfl_sync(0xffffffffu, p, k2);
                if (pk != 0.f) {
                    float4 vv = *(const float4*)(v_sh + k2 * 132 + d0);
                    o[qi][0] += pk * vv.x; o[qi][1] += pk * vv.y;
                    o[qi][2] += pk * vv.z; o[qi][3] += pk * vv.w;
                }
            }
        }
    }

    #pragma unroll
    for (int qi = 0; qi < 4; qi++) {
        const int q = q0 + qrb + qi;
        float4 res;
        if (l[qi] > 0.f) {
            float inv = 1.f / l[qi];
            res = make_float4(o[qi][0] * inv, o[qi][1] * inv,
                              o[qi][2] * inv, o[qi][3] * inv);
        } else {
            res = *(const float4*)(g_vmean + (b * HKVN + n) * HDN + d0);
        }
        *(float4*)(g_o + ((size_t)(b * SS + q)) * DD + h * HDN + d0) = res;
    }
}

// ---------------- launch -----------------------------------------------------
extern "C" void kernel_launch(void* const* d_in, const int* in_sizes, int n_in,
                              void* d_out, int out_size) {
    const float* X  = (const float*)d_in[0];
    const float* Wq = (const float*)d_in[1];
    const float* Wk = (const float*)d_in[2];
    const float* Wv = (const float*)d_in[3];
    const float* Wg = (const float*)d_in[4];
    const float* Wd = (const float*)d_in[5];
    const float* Wo = (const float*)d_in[6];
    float* out = (float*)d_out;

    float *qp, *kp, *vp, *op;
    cudaGetSymbolAddress((void**)&qp, g_q);
    cudaGetSymbolAddress((void**)&kp, g_k);
    cudaGetSymbolAddress((void**)&vp, g_v);
    cudaGetSymbolAddress((void**)&op, g_o);

    cudaFuncSetAttribute(gemm_tf32x3, cudaFuncAttributeMaxDynamicSharedMemorySize, GEMM_SMEM);
    const int attn_smem = 3 * 32 * 132 * 4;
    cudaFuncSetAttribute(attn_kernel, cudaFuncAttributeMaxDynamicSharedMemorySize, attn_smem);

    gemm_tf32x3<<<dim3(DD / 128, MROWS / 128), 256, GEMM_SMEM>>>(X, Wq, qp, MROWS, DD,  DD);
    gemm_tf32x3<<<dim3(KVD / 128, MROWS / 128), 256, GEMM_SMEM>>>(X, Wk, kp, MROWS, KVD, DD);
    gemm_tf32x3<<<dim3(KVD / 128, MROWS / 128), 256, GEMM_SMEM>>>(X, Wv, vp, MROWS, KVD, DD);

    bias_kernel<<<(MROWS * HKVN * 32) / 256, 256>>>(Wg, Wd);
    vmean_kernel<<<BB * HKVN, HDN>>>();

    attn_kernel<<<dim3(SS / 32, HH, BB), 256, attn_smem>>>();

    gemm_tf32x3<<<dim3(DD / 128, MROWS / 128), 256, GEMM_SMEM>>>(op, Wo, out, MROWS, DD, DD);
}

// round 4
// speedup vs baseline: 2.1132x; 1.7393x over previous
#include <cuda_runtime.h>
#include <math.h>
#include <stdint.h>

#define BB   2
#define SS   2048
#define DD   2048
#define HH   16
#define HKVN 4
#define GGN  4
#define HDN  128
#define MROWS (BB*SS)
#define KVD  (HKVN*HDN)   // 512
#define CAP  (SS+32)      // compacted capacity incl. pad

// ---------------- scratch (device globals; no cudaMalloc allowed) ----------
__device__ float g_q[MROWS*DD];
__device__ float g_k[MROWS*KVD];
__device__ float g_v[MROWS*KVD];
__device__ float g_bias[BB*HKVN*SS];
__device__ float g_vmean[BB*HKVN*HDN];
__device__ float g_o[MROWS*DD];
// compacted per (b,n)
__device__ float g_ck[BB*HKVN*CAP*HDN];
__device__ float g_cv[BB*HKVN*CAP*HDN];
__device__ float g_cb[BB*HKVN*CAP];
__device__ int   g_cidx[BB*HKVN*CAP];
__device__ int   g_prefix[BB*HKVN*(SS+1)];

// ---------------- tf32 tensor-core GEMM (SPLIT=1 fast / SPLIT=3 precise) ---
#define ASTR 36
#define BSTR 136
#define A_TILE (128*ASTR)
#define B_TILE (32*BSTR)
#define GEMM_SMEM ((2*A_TILE + 2*B_TILE)*4)   // 71680 bytes

__device__ __forceinline__ uint32_t f2tf(float f) {
    uint32_t u;
    asm("cvt.rna.tf32.f32 %0, %1;" : "=r"(u) : "f"(f));
    return u;
}
__device__ __forceinline__ void split_tf32(float f, uint32_t& hi, uint32_t& lo) {
    uint32_t h;
    asm("cvt.rna.tf32.f32 %0, %1;" : "=r"(h) : "f"(f));
    float r = f - __uint_as_float(h);
    asm("cvt.rna.tf32.f32 %0, %1;" : "=r"(lo) : "f"(r));
    hi = h;
}
__device__ __forceinline__ void mma_tf32(float* c, const uint32_t* a, const uint32_t* b) {
    asm volatile(
        "mma.sync.aligned.m16n8k8.row.col.f32.tf32.tf32.f32 "
        "{%0,%1,%2,%3},{%4,%5,%6,%7},{%8,%9},{%0,%1,%2,%3};"
        : "+f"(c[0]), "+f"(c[1]), "+f"(c[2]), "+f"(c[3])
        : "r"(a[0]), "r"(a[1]), "r"(a[2]), "r"(a[3]), "r"(b[0]), "r"(b[1]));
}
#define CP16(dst, src) asm volatile("cp.async.cg.shared.global [%0], [%1], 16;" :: "r"(dst), "l"(src))

template<int SPLIT>
__global__ __launch_bounds__(256, 2) void gemm_tf32(const float* __restrict__ A,
                                                    const float* __restrict__ B,
                                                    float* __restrict__ C,
                                                    int M, int N, int K) {
    extern __shared__ float sm[];
    float* As = sm;
    float* Bs = sm + 2 * A_TILE;

    const int tid  = threadIdx.x;
    const int wid  = tid >> 5;
    const int lane = tid & 31;
    const int wm   = (wid & 3) << 5;
    const int wn   = (wid >> 2) << 6;
    const int m0   = blockIdx.y << 7;
    const int n0   = blockIdx.x << 7;
    const int lr   = lane >> 2;
    const int lc   = lane & 3;

    float acc[2][8][4];
    #pragma unroll
    for (int mt = 0; mt < 2; mt++)
        #pragma unroll
        for (int nt = 0; nt < 8; nt++)
            #pragma unroll
            for (int i = 0; i < 4; i++) acc[mt][nt][i] = 0.f;

    const int KT = K >> 5;

    auto load_stage = [&](int kt, int s) {
        float* as = As + s * A_TILE;
        float* bs = Bs + s * B_TILE;
        #pragma unroll
        for (int p = 0; p < 4; p++) {
            int idx = tid + (p << 8);
            int r = idx >> 3, kv = (idx & 7) << 2;
            uint32_t dst = (uint32_t)__cvta_generic_to_shared(as + r * ASTR + kv);
            CP16(dst, A + (size_t)(m0 + r) * K + (kt << 5) + kv);
        }
        #pragma unroll
        for (int p = 0; p < 4; p++) {
            int idx = tid + (p << 8);
            int r = idx >> 5, nv = (idx & 31) << 2;
            uint32_t dst = (uint32_t)__cvta_generic_to_shared(bs + r * BSTR + nv);
            CP16(dst, B + (size_t)((kt << 5) + r) * N + n0 + nv);
        }
        asm volatile("cp.async.commit_group;");
    };

    load_stage(0, 0);

    for (int kt = 0; kt < KT; kt++) {
        asm volatile("cp.async.wait_group 0;");
        __syncthreads();
        if (kt + 1 < KT) load_stage(kt + 1, (kt + 1) & 1);

        const float* as = As + (kt & 1) * A_TILE;
        const float* bs = Bs + (kt & 1) * B_TILE;

        #pragma unroll
        for (int ks = 0; ks < 4; ks++) {
            const int kk = ks << 3;
            uint32_t ah[2][4], al[2][4];
            #pragma unroll
            for (int mt = 0; mt < 2; mt++) {
                const float* ap = as + (wm + (mt << 4) + lr) * ASTR + kk + lc;
                if (SPLIT == 3) {
                    split_tf32(ap[0],            ah[mt][0], al[mt][0]);
                    split_tf32(ap[8 * ASTR],     ah[mt][1], al[mt][1]);
                    split_tf32(ap[4],            ah[mt][2], al[mt][2]);
                    split_tf32(ap[8 * ASTR + 4], ah[mt][3], al[mt][3]);
                } else {
                    ah[mt][0] = f2tf(ap[0]);
                    ah[mt][1] = f2tf(ap[8 * ASTR]);
                    ah[mt][2] = f2tf(ap[4]);
                    ah[mt][3] = f2tf(ap[8 * ASTR + 4]);
                }
            }
            #pragma unroll
            for (int nt = 0; nt < 8; nt++) {
                const float* bp = bs + (kk + lc) * BSTR + wn + (nt << 3) + lr;
                uint32_t bh[2], bl[2];
                if (SPLIT == 3) {
                    split_tf32(bp[0],        bh[0], bl[0]);
                    split_tf32(bp[4 * BSTR], bh[1], bl[1]);
                } else {
                    bh[0] = f2tf(bp[0]);
                    bh[1] = f2tf(bp[4 * BSTR]);
                }
                #pragma unroll
                for (int mt = 0; mt < 2; mt++) {
                    mma_tf32(acc[mt][nt], ah[mt], bh);
                    if (SPLIT == 3) {
                        mma_tf32(acc[mt][nt], ah[mt], bl);
                        mma_tf32(acc[mt][nt], al[mt], bh);
                    }
                }
            }
        }
        __syncthreads();
    }

    #pragma unroll
    for (int mt = 0; mt < 2; mt++) {
        #pragma unroll
        for (int nt = 0; nt < 8; nt++) {
            int row = m0 + wm + (mt << 4) + lr;
            int col = n0 + wn + (nt << 3) + (lc << 1);
            *(float2*)&C[(size_t)row * N + col] =
                make_float2(acc[mt][nt][0], acc[mt][nt][1]);
            *(float2*)&C[(size_t)(row + 8) * N + col] =
                make_float2(acc[mt][nt][2], acc[mt][nt][3]);
        }
    }
}

// ---------------- bias: sigmoid(q_flat @ Wg) * (v_flat @ Wd) ---------------
__global__ void bias_kernel(const float* __restrict__ Wg, const float* __restrict__ Wd) {
    int gwarp = (blockIdx.x * blockDim.x + threadIdx.x) >> 5;
    int lane  = threadIdx.x & 31;
    if (gwarp >= MROWS * HKVN) return;
    int n   = gwarp & 3;
    int row = gwarp >> 2;

    const float* qr = g_q + (size_t)row * DD;
    const float* vr = g_v + (size_t)row * KVD;
    float sg = 0.f, sd = 0.f;
    for (int d = lane; d < DD;  d += 32) sg += qr[d] * Wg[d * HKVN + n];
    for (int d = lane; d < KVD; d += 32) sd += vr[d] * Wd[d * HKVN + n];
    #pragma unroll
    for (int off = 16; off; off >>= 1) {
        sg += __shfl_xor_sync(0xffffffffu, sg, off);
        sd += __shfl_xor_sync(0xffffffffu, sd, off);
    }
    if (lane == 0) {
        float bias = sd / (1.f + expf(-sg));
        int b = row / SS, s = row % SS;
        g_bias[(b * HKVN + n) * SS + s] = bias;
    }
}

// ---------------- vmean ------------------------------------------------------
__global__ void vmean_kernel() {
    int bn = blockIdx.x;
    int d  = threadIdx.x;
    int b = bn >> 2, n = bn & 3;
    float s = 0.f;
    #pragma unroll 4
    for (int t = 0; t < SS; t++)
        s += g_v[((size_t)(b * SS + t)) * KVD + n * HDN + d];
    g_vmean[bn * HDN + d] = s * (1.f / SS);
}

// ---------------- compaction: scan, gather, pad -----------------------------
__global__ void scan_kernel() {            // grid 8, block 1024
    __shared__ int wsum[32];
    int bn = blockIdx.x, t = threadIdx.x;
    int lane = t & 31, w = t >> 5;
    const float* bias = g_bias + bn * SS;
    int f0 = bias[2 * t]     > 0.f;
    int f1 = bias[2 * t + 1] > 0.f;
    int v = f0 + f1;
    int s = v;
    #pragma unroll
    for (int off = 1; off < 32; off <<= 1) {
        int u = __shfl_up_sync(0xffffffffu, s, off);
        if (lane >= off) s += u;
    }
    if (lane == 31) wsum[w] = s;
    __syncthreads();
    if (w == 0) {
        int ws = wsum[lane];
        #pragma unroll
        for (int off = 1; off < 32; off <<= 1) {
            int u = __shfl_up_sync(0xffffffffu, ws, off);
            if (lane >= off) ws += u;
        }
        wsum[lane] = ws;
    }
    __syncthreads();
    int base = (w > 0 ? wsum[w - 1] : 0) + s - v;   // exclusive prefix at 2t
    int* pf = g_prefix + bn * (SS + 1);
    if (t == 0) pf[0] = 0;
    pf[2 * t + 1] = base + f0;
    pf[2 * t + 2] = base + f0 + f1;
}

__global__ void gather_kernel() {          // grid (SS/8, 8), block 256
    int bn = blockIdx.y;
    int b = bn >> 2, n = bn & 3;
    int w = threadIdx.x >> 5, lane = threadIdx.x & 31;
    int key = blockIdx.x * 8 + w;
    float bk = g_bias[bn * SS + key];
    if (bk > 0.f) {
        int pos = g_prefix[bn * (SS + 1) + key];
        size_t src = ((size_t)(b * SS + key)) * KVD + n * HDN + lane * 4;
        size_t dst = ((size_t)bn * CAP + pos) * HDN + lane * 4;
        *(float4*)(g_ck + dst) = *(const float4*)(g_k + src);
        *(float4*)(g_cv + dst) = *(const float4*)(g_v + src);
        if (lane == 0) { g_cb[bn * CAP + pos] = bk; g_cidx[bn * CAP + pos] = key; }
    }
}

__global__ void pad_kernel() {             // grid 8, block 1024
    int bn = blockIdx.x;
    int nc = g_prefix[bn * (SS + 1) + SS];
    int r = threadIdx.x >> 5, lane = threadIdx.x & 31;
    int pos = nc + r;
    size_t dst = ((size_t)bn * CAP + pos) * HDN + lane * 4;
    *(float4*)(g_ck + dst) = make_float4(0.f, 0.f, 0.f, 0.f);
    *(float4*)(g_cv + dst) = make_float4(0.f, 0.f, 0.f, 0.f);
    if (lane == 0) { g_cidx[bn * CAP + pos] = 0x7fffffff; g_cb[bn * CAP + pos] = 0.f; }
}

// ---------------- flash attention over compacted keys ----------------------
__global__ void attn_kernel() {
    extern __shared__ float smattn[];
    float* q_sh  = smattn;                  // 32 x 132
    float* k_sh  = smattn + 32 * 132;
    float* v_sh  = smattn + 2 * 32 * 132;
    float* cb_sh = smattn + 3 * 32 * 132;   // 32
    int*   idx_sh = (int*)(cb_sh + 32);     // 32

    const int qtile = blockIdx.x;
    const int h     = blockIdx.y;
    const int b     = blockIdx.z;
    const int n     = h >> 2;
    const int bn    = b * HKVN + n;
    const int q0    = qtile << 5;
    const int tid   = threadIdx.x;
    const int w     = tid >> 5;
    const int lane  = tid & 31;
    const int d0    = lane << 2;
    const int qrb   = w << 2;
    const float scale = 0.0883883476483184f;

    #pragma unroll
    for (int i = 0; i < 16; i++) {
        int idx = tid + i * 256;
        int r = idx >> 7, d = idx & 127;
        q_sh[r * 132 + d] = g_q[((size_t)(b * SS + q0 + r)) * DD + h * HDN + d];
    }

    float m[4], l[4], o[4][4];
    #pragma unroll
    for (int qi = 0; qi < 4; qi++) {
        m[qi] = -INFINITY; l[qi] = 0.f;
        #pragma unroll
        for (int j = 0; j < 4; j++) o[qi][j] = 0.f;
    }

    const int limit  = g_prefix[bn * (SS + 1) + q0 + 32]; // allowed keys < q0+32
    const int ntiles = (limit + 31) >> 5;

    for (int kt = 0; kt < ntiles; kt++) {
        const int kbase = kt << 5;
        __syncthreads();
        #pragma unroll
        for (int i = 0; i < 16; i++) {
            int idx = tid + i * 256;
            int r = idx >> 7, d = idx & 127;
            size_t src = ((size_t)bn * CAP + kbase + r) * HDN + d;
            k_sh[r * 132 + d] = g_ck[src];
            v_sh[r * 132 + d] = g_cv[src];
        }
        if (tid < 32) {
            cb_sh[tid]  = g_cb[bn * CAP + kbase + tid];
            idx_sh[tid] = g_cidx[bn * CAP + kbase + tid];
        }
        __syncthreads();

        const int   kidx = idx_sh[lane];
        const float bk   = cb_sh[lane];

        float s4[4] = {0.f, 0.f, 0.f, 0.f};
        const float4* kp = (const float4*)(k_sh + lane * 132);
        #pragma unroll 8
        for (int c = 0; c < 32; c++) {
            float4 kv = kp[c];
            #pragma unroll
            for (int qi = 0; qi < 4; qi++) {
                float4 qv = ((const float4*)(q_sh + (qrb + qi) * 132))[c];
                s4[qi] += qv.x * kv.x + qv.y * kv.y + qv.z * kv.z + qv.w * kv.w;
            }
        }

        #pragma unroll
        for (int qi = 0; qi < 4; qi++) {
            const int q = q0 + qrb + qi;
            const bool allowed = (kidx <= q);
            float logit = allowed ? (s4[qi] * scale + bk) : -INFINITY;

            float tmax = logit;
            #pragma unroll
            for (int off = 16; off; off >>= 1)
                tmax = fmaxf(tmax, __shfl_xor_sync(0xffffffffu, tmax, off));
            float mnew = fmaxf(m[qi], tmax);
            if (mnew == -INFINITY) continue;

            float corr = (m[qi] == -INFINITY) ? 0.f : __expf(m[qi] - mnew);
            float p    = allowed ? __expf(logit - mnew) : 0.f;
            float psum = p;
            #pragma unroll
            for (int off = 16; off; off >>= 1)
                psum += __shfl_xor_sync(0xffffffffu, psum, off);
            l[qi] = l[qi] * corr + psum;
            m[qi] = mnew;
            #pragma unroll
            for (int j = 0; j < 4; j++) o[qi][j] *= corr;

            #pragma unroll 8
            for (int k2 = 0; k2 < 32; k2++) {
                float pk = __shfl_sync(0xffffffffu, p, k2);
                if (pk != 0.f) {
                    float4 vv = *(const float4*)(v_sh + k2 * 132 + d0);
                    o[qi][0] += pk * vv.x; o[qi][1] += pk * vv.y;
                    o[qi][2] += pk * vv.z; o[qi][3] += pk * vv.w;
                }
            }
        }
    }

    #pragma unroll
    for (int qi = 0; qi < 4; qi++) {
        const int q = q0 + qrb + qi;
        float4 res;
        if (l[qi] > 0.f) {
            float inv = 1.f / l[qi];
            res = make_float4(o[qi][0] * inv, o[qi][1] * inv,
                              o[qi][2] * inv, o[qi][3] * inv);
        } else {
            res = *(const float4*)(g_vmean + bn * HDN + d0);
        }
        *(float4*)(g_o + ((size_t)(b * SS + q)) * DD + h * HDN + d0) = res;
    }
}

// ---------------- launch -----------------------------------------------------
extern "C" void kernel_launch(void* const* d_in, const int* in_sizes, int n_in,
                              void* d_out, int out_size) {
    const float* X  = (const float*)d_in[0];
    const float* Wq = (const float*)d_in[1];
    const float* Wk = (const float*)d_in[2];
    const float* Wv = (const float*)d_in[3];
    const float* Wg = (const float*)d_in[4];
    const float* Wd = (const float*)d_in[5];
    const float* Wo = (const float*)d_in[6];
    float* out = (float*)d_out;

    float *qp, *kp, *vp, *op;
    cudaGetSymbolAddress((void**)&qp, g_q);
    cudaGetSymbolAddress((void**)&kp, g_k);
    cudaGetSymbolAddress((void**)&vp, g_v);
    cudaGetSymbolAddress((void**)&op, g_o);

    cudaFuncSetAttribute(gemm_tf32<1>, cudaFuncAttributeMaxDynamicSharedMemorySize, GEMM_SMEM);
    cudaFuncSetAttribute(gemm_tf32<3>, cudaFuncAttributeMaxDynamicSharedMemorySize, GEMM_SMEM);
    const int attn_smem = 3 * 32 * 132 * 4 + 32 * 8;
    cudaFuncSetAttribute(attn_kernel, cudaFuncAttributeMaxDynamicSharedMemorySize, attn_smem);

    // projections: single-pass tf32 for smooth paths, 3xTF32 for mask-critical V
    gemm_tf32<1><<<dim3(DD / 128, MROWS / 128), 256, GEMM_SMEM>>>(X, Wq, qp, MROWS, DD,  DD);
    gemm_tf32<1><<<dim3(KVD / 128, MROWS / 128), 256, GEMM_SMEM>>>(X, Wk, kp, MROWS, KVD, DD);
    gemm_tf32<3><<<dim3(KVD / 128, MROWS / 128), 256, GEMM_SMEM>>>(X, Wv, vp, MROWS, KVD, DD);

    bias_kernel<<<(MROWS * HKVN * 32) / 256, 256>>>(Wg, Wd);
    vmean_kernel<<<BB * HKVN, HDN>>>();

    // compact allowed keys per (b, kv-head)
    scan_kernel<<<BB * HKVN, 1024>>>();
    gather_kernel<<<dim3(SS / 8, BB * HKVN), 256>>>();
    pad_kernel<<<BB * HKVN, 1024>>>();

    attn_kernel<<<dim3(SS / 32, HH, BB), 256, attn_smem>>>();

    gemm_tf32<1><<<dim3(DD / 128, MROWS / 128), 256, GEMM_SMEM>>>(op, Wo, out, MROWS, DD, DD);
}

// round 5
// speedup vs baseline: 2.7986x; 1.3244x over previous
#include <cuda_runtime.h>
#include <math.h>
#include <stdint.h>

#define BB   2
#define SS   2048
#define DD   2048
#define HH   16
#define HKVN 4
#define GGN  4
#define HDN  128
#define MROWS (BB*SS)
#define KVD  (HKVN*HDN)   // 512
#define CAP  (SS+32)

// ---------------- scratch ----------------------------------------------------
__device__ float g_q[MROWS*DD];
__device__ float g_k[MROWS*KVD];
__device__ float g_v[MROWS*KVD];
__device__ float g_bias[BB*HKVN*SS];
__device__ float g_vmean[BB*HKVN*HDN];
__device__ float g_o[MROWS*DD];
// tf32-pre-rounded operands
__device__ float g_xr[MROWS*DD];
__device__ float g_wqr[DD*DD];
__device__ float g_wkr[DD*KVD];
__device__ float g_wvr[DD*KVD];
__device__ float g_wor[DD*DD];
// fused small weights (fp32)
__device__ float g_wqg[DD*HKVN];
__device__ float g_wvd[DD*HKVN];
// compaction
__device__ float g_ck[BB*HKVN*CAP*HDN];
__device__ float g_cv[BB*HKVN*CAP*HDN];
__device__ float g_cb[BB*HKVN*CAP];
__device__ int   g_cidx[BB*HKVN*CAP];
__device__ int   g_prefix[BB*HKVN*(SS+1)];

__device__ __forceinline__ uint32_t f2tf(float f) {
    uint32_t u;
    asm("cvt.rna.tf32.f32 %0, %1;" : "=r"(u) : "f"(f));
    return u;
}

// ---------------- elementwise tf32 rounding ---------------------------------
__global__ void round_tf32(const float* __restrict__ in, float* __restrict__ out, int n4) {
    int i = blockIdx.x * blockDim.x + threadIdx.x;
    if (i < n4) {
        float4 v = ((const float4*)in)[i];
        v.x = __uint_as_float(f2tf(v.x));
        v.y = __uint_as_float(f2tf(v.y));
        v.z = __uint_as_float(f2tf(v.z));
        v.w = __uint_as_float(f2tf(v.w));
        ((float4*)out)[i] = v;
    }
}

// ---------------- fuse: out[d][n] = sum_j A[d][j]*B[j][n], n<4 (fp32) -------
__global__ void fuse_w(const float* __restrict__ A, const float* __restrict__ B,
                       float* __restrict__ out, int K) {
    int d    = (blockIdx.x * blockDim.x + threadIdx.x) >> 5;
    int lane = threadIdx.x & 31;
    if (d >= DD) return;
    float a0 = 0.f, a1 = 0.f, a2 = 0.f, a3 = 0.f;
    const float* ar = A + (size_t)d * K;
    for (int j = lane; j < K; j += 32) {
        float a = ar[j];
        float4 b = *(const float4*)&B[j * 4];
        a0 += a * b.x; a1 += a * b.y; a2 += a * b.z; a3 += a * b.w;
    }
    #pragma unroll
    for (int off = 16; off; off >>= 1) {
        a0 += __shfl_xor_sync(0xffffffffu, a0, off);
        a1 += __shfl_xor_sync(0xffffffffu, a1, off);
        a2 += __shfl_xor_sync(0xffffffffu, a2, off);
        a3 += __shfl_xor_sync(0xffffffffu, a3, off);
    }
    if (lane == 0) { float4 o = make_float4(a0, a1, a2, a3); *(float4*)&out[d * 4] = o; }
}

// ---------------- bias from X (fp32 exact mask) ------------------------------
// one warp per row: gate_n = X[row]·Wqg[:,n], delta_n = X[row]·Wvd[:,n]
__global__ void bias2_kernel(const float* __restrict__ X) {
    int row  = (blockIdx.x * blockDim.x + threadIdx.x) >> 5;
    int lane = threadIdx.x & 31;
    if (row >= MROWS) return;
    const float* xr = X + (size_t)row * DD;
    float sg[4] = {0.f,0.f,0.f,0.f}, sd[4] = {0.f,0.f,0.f,0.f};
    for (int d = lane; d < DD; d += 32) {
        float x = xr[d];
        float4 wg = *(const float4*)&g_wqg[d * 4];
        float4 wd = *(const float4*)&g_wvd[d * 4];
        sg[0] += x * wg.x; sg[1] += x * wg.y; sg[2] += x * wg.z; sg[3] += x * wg.w;
        sd[0] += x * wd.x; sd[1] += x * wd.y; sd[2] += x * wd.z; sd[3] += x * wd.w;
    }
    #pragma unroll
    for (int off = 16; off; off >>= 1)
        #pragma unroll
        for (int n = 0; n < 4; n++) {
            sg[n] += __shfl_xor_sync(0xffffffffu, sg[n], off);
            sd[n] += __shfl_xor_sync(0xffffffffu, sd[n], off);
        }
    if (lane == 0) {
        int b = row / SS, s = row % SS;
        #pragma unroll
        for (int n = 0; n < 4; n++)
            g_bias[(b * HKVN + n) * SS + s] = sd[n] / (1.f + expf(-sg[n]));
    }
}

// ---------------- tf32 GEMM, operands pre-rounded (no cvt in loop) ----------
#define ASTR 36
#define BSTR 136
#define A_TILE (128*ASTR)
#define B_TILE (32*BSTR)
#define GEMM_SMEM ((2*A_TILE + 2*B_TILE)*4)

__device__ __forceinline__ void mma_tf32(float* c, const uint32_t* a, const uint32_t* b) {
    asm volatile(
        "mma.sync.aligned.m16n8k8.row.col.f32.tf32.tf32.f32 "
        "{%0,%1,%2,%3},{%4,%5,%6,%7},{%8,%9},{%0,%1,%2,%3};"
        : "+f"(c[0]), "+f"(c[1]), "+f"(c[2]), "+f"(c[3])
        : "r"(a[0]), "r"(a[1]), "r"(a[2]), "r"(a[3]), "r"(b[0]), "r"(b[1]));
}
#define CP16(dst, src) asm volatile("cp.async.cg.shared.global [%0], [%1], 16;" :: "r"(dst), "l"(src))

__global__ __launch_bounds__(256, 2) void gemm_tf32(const float* __restrict__ A,
                                                    const float* __restrict__ B,
                                                    float* __restrict__ C,
                                                    int M, int N, int K) {
    extern __shared__ float sm[];
    float* As = sm;
    float* Bs = sm + 2 * A_TILE;

    const int tid  = threadIdx.x;
    const int wid  = tid >> 5;
    const int lane = tid & 31;
    const int wm   = (wid & 3) << 5;
    const int wn   = (wid >> 2) << 6;
    const int m0   = blockIdx.y << 7;
    const int n0   = blockIdx.x << 7;
    const int lr   = lane >> 2;
    const int lc   = lane & 3;

    float acc[2][8][4];
    #pragma unroll
    for (int mt = 0; mt < 2; mt++)
        #pragma unroll
        for (int nt = 0; nt < 8; nt++)
            #pragma unroll
            for (int i = 0; i < 4; i++) acc[mt][nt][i] = 0.f;

    const int KT = K >> 5;

    auto load_stage = [&](int kt, int s) {
        float* as = As + s * A_TILE;
        float* bs = Bs + s * B_TILE;
        #pragma unroll
        for (int p = 0; p < 4; p++) {
            int idx = tid + (p << 8);
            int r = idx >> 3, kv = (idx & 7) << 2;
            uint32_t dst = (uint32_t)__cvta_generic_to_shared(as + r * ASTR + kv);
            CP16(dst, A + (size_t)(m0 + r) * K + (kt << 5) + kv);
        }
        #pragma unroll
        for (int p = 0; p < 4; p++) {
            int idx = tid + (p << 8);
            int r = idx >> 5, nv = (idx & 31) << 2;
            uint32_t dst = (uint32_t)__cvta_generic_to_shared(bs + r * BSTR + nv);
            CP16(dst, B + (size_t)((kt << 5) + r) * N + n0 + nv);
        }
        asm volatile("cp.async.commit_group;");
    };

    load_stage(0, 0);

    for (int kt = 0; kt < KT; kt++) {
        asm volatile("cp.async.wait_group 0;");
        __syncthreads();
        if (kt + 1 < KT) load_stage(kt + 1, (kt + 1) & 1);

        const float* as = As + (kt & 1) * A_TILE;
        const float* bs = Bs + (kt & 1) * B_TILE;

        #pragma unroll
        for (int ks = 0; ks < 4; ks++) {
            const int kk = ks << 3;
            uint32_t afr[2][4];
            #pragma unroll
            for (int mt = 0; mt < 2; mt++) {
                const uint32_t* ap = (const uint32_t*)(as + (wm + (mt << 4) + lr) * ASTR + kk + lc);
                afr[mt][0] = ap[0];
                afr[mt][1] = ap[8 * ASTR];
                afr[mt][2] = ap[4];
                afr[mt][3] = ap[8 * ASTR + 4];
            }
            #pragma unroll
            for (int nt = 0; nt < 8; nt++) {
                const uint32_t* bp = (const uint32_t*)(bs + (kk + lc) * BSTR + wn + (nt << 3) + lr);
                uint32_t bfr[2];
                bfr[0] = bp[0];
                bfr[1] = bp[4 * BSTR];
                mma_tf32(acc[0][nt], afr[0], bfr);
                mma_tf32(acc[1][nt], afr[1], bfr);
            }
        }
        __syncthreads();
    }

    #pragma unroll
    for (int mt = 0; mt < 2; mt++) {
        #pragma unroll
        for (int nt = 0; nt < 8; nt++) {
            int row = m0 + wm + (mt << 4) + lr;
            int col = n0 + wn + (nt << 3) + (lc << 1);
            *(float2*)&C[(size_t)row * N + col] =
                make_float2(acc[mt][nt][0], acc[mt][nt][1]);
            *(float2*)&C[(size_t)(row + 8) * N + col] =
                make_float2(acc[mt][nt][2], acc[mt][nt][3]);
        }
    }
}

// ---------------- vmean ------------------------------------------------------
__global__ void vmean_kernel() {
    int bn = blockIdx.x;
    int d  = threadIdx.x;
    int b = bn >> 2, n = bn & 3;
    float s = 0.f;
    #pragma unroll 4
    for (int t = 0; t < SS; t++)
        s += g_v[((size_t)(b * SS + t)) * KVD + n * HDN + d];
    g_vmean[bn * HDN + d] = s * (1.f / SS);
}

// ---------------- compaction -------------------------------------------------
__global__ void scan_kernel() {
    __shared__ int wsum[32];
    int bn = blockIdx.x, t = threadIdx.x;
    int lane = t & 31, w = t >> 5;
    const float* bias = g_bias + bn * SS;
    int f0 = bias[2 * t]     > 0.f;
    int f1 = bias[2 * t + 1] > 0.f;
    int v = f0 + f1;
    int s = v;
    #pragma unroll
    for (int off = 1; off < 32; off <<= 1) {
        int u = __shfl_up_sync(0xffffffffu, s, off);
        if (lane >= off) s += u;
    }
    if (lane == 31) wsum[w] = s;
    __syncthreads();
    if (w == 0) {
        int ws = wsum[lane];
        #pragma unroll
        for (int off = 1; off < 32; off <<= 1) {
            int u = __shfl_up_sync(0xffffffffu, ws, off);
            if (lane >= off) ws += u;
        }
        wsum[lane] = ws;
    }
    __syncthreads();
    int base = (w > 0 ? wsum[w - 1] : 0) + s - v;
    int* pf = g_prefix + bn * (SS + 1);
    if (t == 0) pf[0] = 0;
    pf[2 * t + 1] = base + f0;
    pf[2 * t + 2] = base + f0 + f1;
}

__global__ void gather_kernel() {
    int bn = blockIdx.y;
    int b = bn >> 2, n = bn & 3;
    int w = threadIdx.x >> 5, lane = threadIdx.x & 31;
    int key = blockIdx.x * 8 + w;
    float bk = g_bias[bn * SS + key];
    if (bk > 0.f) {
        int pos = g_prefix[bn * (SS + 1) + key];
        size_t src = ((size_t)(b * SS + key)) * KVD + n * HDN + lane * 4;
        size_t dst = ((size_t)bn * CAP + pos) * HDN + lane * 4;
        *(float4*)(g_ck + dst) = *(const float4*)(g_k + src);
        *(float4*)(g_cv + dst) = *(const float4*)(g_v + src);
        if (lane == 0) { g_cb[bn * CAP + pos] = bk; g_cidx[bn * CAP + pos] = key; }
    }
}

__global__ void pad_kernel() {
    int bn = blockIdx.x;
    int nc = g_prefix[bn * (SS + 1) + SS];
    int r = threadIdx.x >> 5, lane = threadIdx.x & 31;
    int pos = nc + r;
    size_t dst = ((size_t)bn * CAP + pos) * HDN + lane * 4;
    *(float4*)(g_ck + dst) = make_float4(0.f, 0.f, 0.f, 0.f);
    *(float4*)(g_cv + dst) = make_float4(0.f, 0.f, 0.f, 0.f);
    if (lane == 0) { g_cidx[bn * CAP + pos] = 0x7fffffff; g_cb[bn * CAP + pos] = 0.f; }
}

// ---------------- flash attention over compacted keys ----------------------
__global__ void attn_kernel() {
    extern __shared__ float smattn[];
    float* q_sh  = smattn;
    float* k_sh  = smattn + 32 * 132;
    float* v_sh  = smattn + 2 * 32 * 132;
    float* cb_sh = smattn + 3 * 32 * 132;
    int*   idx_sh = (int*)(cb_sh + 32);

    const int qtile = blockIdx.x;
    const int h     = blockIdx.y;
    const int b     = blockIdx.z;
    const int n     = h >> 2;
    const int bn    = b * HKVN + n;
    const int q0    = qtile << 5;
    const int tid   = threadIdx.x;
    const int w     = tid >> 5;
    const int lane  = tid & 31;
    const int d0    = lane << 2;
    const int qrb   = w << 2;
    const float scale = 0.0883883476483184f;

    #pragma unroll
    for (int i = 0; i < 16; i++) {
        int idx = tid + i * 256;
        int r = idx >> 7, d = idx & 127;
        q_sh[r * 132 + d] = g_q[((size_t)(b * SS + q0 + r)) * DD + h * HDN + d];
    }

    float m[4], l[4], o[4][4];
    #pragma unroll
    for (int qi = 0; qi < 4; qi++) {
        m[qi] = -INFINITY; l[qi] = 0.f;
        #pragma unroll
        for (int j = 0; j < 4; j++) o[qi][j] = 0.f;
    }

    const int limit  = g_prefix[bn * (SS + 1) + q0 + 32];
    const int ntiles = (limit + 31) >> 5;

    for (int kt = 0; kt < ntiles; kt++) {
        const int kbase = kt << 5;
        __syncthreads();
        #pragma unroll
        for (int i = 0; i < 16; i++) {
            int idx = tid + i * 256;
            int r = idx >> 7, d = idx & 127;
            size_t src = ((size_t)bn * CAP + kbase + r) * HDN + d;
            k_sh[r * 132 + d] = g_ck[src];
            v_sh[r * 132 + d] = g_cv[src];
        }
        if (tid < 32) {
            cb_sh[tid]  = g_cb[bn * CAP + kbase + tid];
            idx_sh[tid] = g_cidx[bn * CAP + kbase + tid];
        }
        __syncthreads();

        const int   kidx = idx_sh[lane];
        const float bk   = cb_sh[lane];

        float s4[4] = {0.f, 0.f, 0.f, 0.f};
        const float4* kp = (const float4*)(k_sh + lane * 132);
        #pragma unroll 8
        for (int c = 0; c < 32; c++) {
            float4 kv = kp[c];
            #pragma unroll
            for (int qi = 0; qi < 4; qi++) {
                float4 qv = ((const float4*)(q_sh + (qrb + qi) * 132))[c];
                s4[qi] += qv.x * kv.x + qv.y * kv.y + qv.z * kv.z + qv.w * kv.w;
            }
        }

        float p[4];
        #pragma unroll
        for (int qi = 0; qi < 4; qi++) {
            const int q = q0 + qrb + qi;
            const bool allowed = (kidx <= q);
            float logit = allowed ? (s4[qi] * scale + bk) : -INFINITY;

            float tmax = logit;
            #pragma unroll
            for (int off = 16; off; off >>= 1)
                tmax = fmaxf(tmax, __shfl_xor_sync(0xffffffffu, tmax, off));
            float mnew = fmaxf(m[qi], tmax);
            if (mnew == -INFINITY) { p[qi] = 0.f; continue; }

            float corr = (m[qi] == -INFINITY) ? 0.f : __expf(m[qi] - mnew);
            p[qi] = allowed ? __expf(logit - mnew) : 0.f;
            float psum = p[qi];
            #pragma unroll
            for (int off = 16; off; off >>= 1)
                psum += __shfl_xor_sync(0xffffffffu, psum, off);
            l[qi] = l[qi] * corr + psum;
            m[qi] = mnew;
            #pragma unroll
            for (int j = 0; j < 4; j++) o[qi][j] *= corr;
        }

        // PV: k2 outer so V fragment is loaded once per key
        #pragma unroll 4
        for (int k2 = 0; k2 < 32; k2++) {
            float4 vv = *(const float4*)(v_sh + k2 * 132 + d0);
            #pragma unroll
            for (int qi = 0; qi < 4; qi++) {
                float pk = __shfl_sync(0xffffffffu, p[qi], k2);
                o[qi][0] += pk * vv.x; o[qi][1] += pk * vv.y;
                o[qi][2] += pk * vv.z; o[qi][3] += pk * vv.w;
            }
        }
    }

    #pragma unroll
    for (int qi = 0; qi < 4; qi++) {
        const int q = q0 + qrb + qi;
        float4 res;
        if (l[qi] > 0.f) {
            float inv = 1.f / l[qi];
            res = make_float4(o[qi][0] * inv, o[qi][1] * inv,
                              o[qi][2] * inv, o[qi][3] * inv);
        } else {
            res = *(const float4*)(g_vmean + bn * HDN + d0);
        }
        // emit pre-rounded tf32 so the O-projection GEMM needs no cvt
        res.x = __uint_as_float(f2tf(res.x));
        res.y = __uint_as_float(f2tf(res.y));
        res.z = __uint_as_float(f2tf(res.z));
        res.w = __uint_as_float(f2tf(res.w));
        *(float4*)(g_o + ((size_t)(b * SS + q)) * DD + h * HDN + d0) = res;
    }
}

// ---------------- launch -----------------------------------------------------
extern "C" void kernel_launch(void* const* d_in, const int* in_sizes, int n_in,
                              void* d_out, int out_size) {
    const float* X  = (const float*)d_in[0];
    const float* Wq = (const float*)d_in[1];
    const float* Wk = (const float*)d_in[2];
    const float* Wv = (const float*)d_in[3];
    const float* Wg = (const float*)d_in[4];
    const float* Wd = (const float*)d_in[5];
    const float* Wo = (const float*)d_in[6];
    float* out = (float*)d_out;

    float *qp, *kp, *vp, *op, *xr, *wqr, *wkr, *wvr, *wor, *wqg, *wvd;
    cudaGetSymbolAddress((void**)&qp, g_q);
    cudaGetSymbolAddress((void**)&kp, g_k);
    cudaGetSymbolAddress((void**)&vp, g_v);
    cudaGetSymbolAddress((void**)&op, g_o);
    cudaGetSymbolAddress((void**)&xr, g_xr);
    cudaGetSymbolAddress((void**)&wqr, g_wqr);
    cudaGetSymbolAddress((void**)&wkr, g_wkr);
    cudaGetSymbolAddress((void**)&wvr, g_wvr);
    cudaGetSymbolAddress((void**)&wor, g_wor);
    cudaGetSymbolAddress((void**)&wqg, g_wqg);
    cudaGetSymbolAddress((void**)&wvd, g_wvd);

    cudaFuncSetAttribute(gemm_tf32, cudaFuncAttributeMaxDynamicSharedMemorySize, GEMM_SMEM);
    const int attn_smem = 3 * 32 * 132 * 4 + 32 * 8;
    cudaFuncSetAttribute(attn_kernel, cudaFuncAttributeMaxDynamicSharedMemorySize, attn_smem);

    // pre-round operands to tf32 (elementwise)
    round_tf32<<<(MROWS*DD/4 + 255)/256, 256>>>(X,  xr,  MROWS*DD/4);
    round_tf32<<<(DD*DD/4    + 255)/256, 256>>>(Wq, wqr, DD*DD/4);
    round_tf32<<<(DD*KVD/4   + 255)/256, 256>>>(Wk, wkr, DD*KVD/4);
    round_tf32<<<(DD*KVD/4   + 255)/256, 256>>>(Wv, wvr, DD*KVD/4);
    round_tf32<<<(DD*DD/4    + 255)/256, 256>>>(Wo, wor, DD*DD/4);

    // fused small weights (fp32 exact)
    fuse_w<<<(DD*32 + 255)/256, 256>>>(Wq, Wg, wqg, DD);
    fuse_w<<<(DD*32 + 255)/256, 256>>>(Wv, Wd, wvd, KVD);

    // bias from original fp32 X -> exact mask
    bias2_kernel<<<(MROWS*32 + 255)/256, 256>>>(X);

    // projections (all single-pass tf32, no cvt in loop)
    gemm_tf32<<<dim3(DD / 128, MROWS / 128), 256, GEMM_SMEM>>>(xr, wqr, qp, MROWS, DD,  DD);
    gemm_tf32<<<dim3(KVD / 128, MROWS / 128), 256, GEMM_SMEM>>>(xr, wkr, kp, MROWS, KVD, DD);
    gemm_tf32<<<dim3(KVD / 128, MROWS / 128), 256, GEMM_SMEM>>>(xr, wvr, vp, MROWS, KVD, DD);

    vmean_kernel<<<BB * HKVN, HDN>>>();

    scan_kernel<<<BB * HKVN, 1024>>>();
    gather_kernel<<<dim3(SS / 8, BB * HKVN), 256>>>();
    pad_kernel<<<BB * HKVN, 1024>>>();

    attn_kernel<<<dim3(SS / 32, HH, BB), 256, attn_smem>>>();

    gemm_tf32<<<dim3(DD / 128, MROWS / 128), 256, GEMM_SMEM>>>(op, wor, out, MROWS, DD, DD);
}

// round 6
// speedup vs baseline: 4.4568x; 1.5925x over previous
#include <cuda_runtime.h>
#include <math.h>
#include <stdint.h>

#define BB   2
#define SS   2048
#define DD   2048
#define HH   16
#define HKVN 4
#define GGN  4
#define HDN  128
#define MROWS (BB*SS)
#define KVD  (HKVN*HDN)   // 512
#define CAP  (SS+32)

// ---------------- scratch ----------------------------------------------------
__device__ float g_q[MROWS*DD];
__device__ float g_k[MROWS*KVD];
__device__ float g_v[MROWS*KVD];
__device__ float g_bias[BB*HKVN*SS];
__device__ float g_vmean[BB*HKVN*HDN];
__device__ float g_o[MROWS*DD];
__device__ float g_xr[MROWS*DD];
__device__ float g_wqr[DD*DD];
__device__ float g_wkr[DD*KVD];
__device__ float g_wvr[DD*KVD];
__device__ float g_wor[DD*DD];
__device__ float g_wqg[DD*HKVN];
__device__ float g_wvd[DD*HKVN];
__device__ float g_ck[BB*HKVN*CAP*HDN];
__device__ float g_cv[BB*HKVN*CAP*HDN];
__device__ float g_cb[BB*HKVN*CAP];
__device__ int   g_cidx[BB*HKVN*CAP];
__device__ int   g_prefix[BB*HKVN*(SS+1)];

__device__ __forceinline__ uint32_t f2tf(float f) {
    uint32_t u;
    asm("cvt.rna.tf32.f32 %0, %1;" : "=r"(u) : "f"(f));
    return u;
}
__device__ __forceinline__ void mma_tf32(float* c, const uint32_t* a, const uint32_t* b) {
    asm volatile(
        "mma.sync.aligned.m16n8k8.row.col.f32.tf32.tf32.f32 "
        "{%0,%1,%2,%3},{%4,%5,%6,%7},{%8,%9},{%0,%1,%2,%3};"
        : "+f"(c[0]), "+f"(c[1]), "+f"(c[2]), "+f"(c[3])
        : "r"(a[0]), "r"(a[1]), "r"(a[2]), "r"(a[3]), "r"(b[0]), "r"(b[1]));
}
#define CP16(dst, src) asm volatile("cp.async.cg.shared.global [%0], [%1], 16;" :: "r"(dst), "l"(src))

// ---------------- elementwise tf32 rounding ---------------------------------
__global__ void round_tf32(const float* __restrict__ in, float* __restrict__ out, int n4) {
    int i = blockIdx.x * blockDim.x + threadIdx.x;
    if (i < n4) {
        float4 v = ((const float4*)in)[i];
        v.x = __uint_as_float(f2tf(v.x));
        v.y = __uint_as_float(f2tf(v.y));
        v.z = __uint_as_float(f2tf(v.z));
        v.w = __uint_as_float(f2tf(v.w));
        ((float4*)out)[i] = v;
    }
}

// ---------------- fuse: out[d][n] = sum_j A[d][j]*B[j][n], n<4 (fp32) -------
__global__ void fuse_w(const float* __restrict__ A, const float* __restrict__ B,
                       float* __restrict__ out, int K) {
    int d    = (blockIdx.x * blockDim.x + threadIdx.x) >> 5;
    int lane = threadIdx.x & 31;
    if (d >= DD) return;
    float a0 = 0.f, a1 = 0.f, a2 = 0.f, a3 = 0.f;
    const float* ar = A + (size_t)d * K;
    for (int j = lane; j < K; j += 32) {
        float a = ar[j];
        float4 b = *(const float4*)&B[j * 4];
        a0 += a * b.x; a1 += a * b.y; a2 += a * b.z; a3 += a * b.w;
    }
    #pragma unroll
    for (int off = 16; off; off >>= 1) {
        a0 += __shfl_xor_sync(0xffffffffu, a0, off);
        a1 += __shfl_xor_sync(0xffffffffu, a1, off);
        a2 += __shfl_xor_sync(0xffffffffu, a2, off);
        a3 += __shfl_xor_sync(0xffffffffu, a3, off);
    }
    if (lane == 0) { float4 o = make_float4(a0, a1, a2, a3); *(float4*)&out[d * 4] = o; }
}

// ---------------- bias from X (fp32 exact mask) ------------------------------
__global__ void bias2_kernel(const float* __restrict__ X) {
    int row  = (blockIdx.x * blockDim.x + threadIdx.x) >> 5;
    int lane = threadIdx.x & 31;
    if (row >= MROWS) return;
    const float* xr = X + (size_t)row * DD;
    float sg[4] = {0.f,0.f,0.f,0.f}, sd[4] = {0.f,0.f,0.f,0.f};
    for (int d = lane; d < DD; d += 32) {
        float x = xr[d];
        float4 wg = *(const float4*)&g_wqg[d * 4];
        float4 wd = *(const float4*)&g_wvd[d * 4];
        sg[0] += x * wg.x; sg[1] += x * wg.y; sg[2] += x * wg.z; sg[3] += x * wg.w;
        sd[0] += x * wd.x; sd[1] += x * wd.y; sd[2] += x * wd.z; sd[3] += x * wd.w;
    }
    #pragma unroll
    for (int off = 16; off; off >>= 1)
        #pragma unroll
        for (int n = 0; n < 4; n++) {
            sg[n] += __shfl_xor_sync(0xffffffffu, sg[n], off);
            sd[n] += __shfl_xor_sync(0xffffffffu, sd[n], off);
        }
    if (lane == 0) {
        int b = row / SS, s = row % SS;
        #pragma unroll
        for (int n = 0; n < 4; n++)
            g_bias[(b * HKVN + n) * SS + s] = sd[n] / (1.f + expf(-sg[n]));
    }
}

// ---------------- tf32 GEMM (pre-rounded operands) --------------------------
#define ASTR 36
#define BSTR 136
#define A_TILE (128*ASTR)
#define B_TILE (32*BSTR)
#define GEMM_SMEM ((2*A_TILE + 2*B_TILE)*4)

__global__ __launch_bounds__(256, 2) void gemm_tf32(const float* __restrict__ A,
                                                    const float* __restrict__ B,
                                                    float* __restrict__ C,
                                                    int M, int N, int K) {
    extern __shared__ float sm[];
    float* As = sm;
    float* Bs = sm + 2 * A_TILE;

    const int tid  = threadIdx.x;
    const int wid  = tid >> 5;
    const int lane = tid & 31;
    const int wm   = (wid & 3) << 5;
    const int wn   = (wid >> 2) << 6;
    const int m0   = blockIdx.y << 7;
    const int n0   = blockIdx.x << 7;
    const int lr   = lane >> 2;
    const int lc   = lane & 3;

    float acc[2][8][4];
    #pragma unroll
    for (int mt = 0; mt < 2; mt++)
        #pragma unroll
        for (int nt = 0; nt < 8; nt++)
            #pragma unroll
            for (int i = 0; i < 4; i++) acc[mt][nt][i] = 0.f;

    const int KT = K >> 5;

    auto load_stage = [&](int kt, int s) {
        float* as = As + s * A_TILE;
        float* bs = Bs + s * B_TILE;
        #pragma unroll
        for (int p = 0; p < 4; p++) {
            int idx = tid + (p << 8);
            int r = idx >> 3, kv = (idx & 7) << 2;
            uint32_t dst = (uint32_t)__cvta_generic_to_shared(as + r * ASTR + kv);
            CP16(dst, A + (size_t)(m0 + r) * K + (kt << 5) + kv);
        }
        #pragma unroll
        for (int p = 0; p < 4; p++) {
            int idx = tid + (p << 8);
            int r = idx >> 5, nv = (idx & 31) << 2;
            uint32_t dst = (uint32_t)__cvta_generic_to_shared(bs + r * BSTR + nv);
            CP16(dst, B + (size_t)((kt << 5) + r) * N + n0 + nv);
        }
        asm volatile("cp.async.commit_group;");
    };

    load_stage(0, 0);

    for (int kt = 0; kt < KT; kt++) {
        asm volatile("cp.async.wait_group 0;");
        __syncthreads();
        if (kt + 1 < KT) load_stage(kt + 1, (kt + 1) & 1);

        const float* as = As + (kt & 1) * A_TILE;
        const float* bs = Bs + (kt & 1) * B_TILE;

        #pragma unroll
        for (int ks = 0; ks < 4; ks++) {
            const int kk = ks << 3;
            uint32_t afr[2][4];
            #pragma unroll
            for (int mt = 0; mt < 2; mt++) {
                const uint32_t* ap = (const uint32_t*)(as + (wm + (mt << 4) + lr) * ASTR + kk + lc);
                afr[mt][0] = ap[0];
                afr[mt][1] = ap[8 * ASTR];
                afr[mt][2] = ap[4];
                afr[mt][3] = ap[8 * ASTR + 4];
            }
            #pragma unroll
            for (int nt = 0; nt < 8; nt++) {
                const uint32_t* bp = (const uint32_t*)(bs + (kk + lc) * BSTR + wn + (nt << 3) + lr);
                uint32_t bfr[2];
                bfr[0] = bp[0];
                bfr[1] = bp[4 * BSTR];
                mma_tf32(acc[0][nt], afr[0], bfr);
                mma_tf32(acc[1][nt], afr[1], bfr);
            }
        }
        __syncthreads();
    }

    #pragma unroll
    for (int mt = 0; mt < 2; mt++) {
        #pragma unroll
        for (int nt = 0; nt < 8; nt++) {
            int row = m0 + wm + (mt << 4) + lr;
            int col = n0 + wn + (nt << 3) + (lc << 1);
            *(float2*)&C[(size_t)row * N + col] =
                make_float2(acc[mt][nt][0], acc[mt][nt][1]);
            *(float2*)&C[(size_t)(row + 8) * N + col] =
                make_float2(acc[mt][nt][2], acc[mt][nt][3]);
        }
    }
}

// ---------------- vmean ------------------------------------------------------
__global__ void vmean_kernel() {
    int bn = blockIdx.x;
    int d  = threadIdx.x;
    int b = bn >> 2, n = bn & 3;
    float s = 0.f;
    #pragma unroll 4
    for (int t = 0; t < SS; t++)
        s += g_v[((size_t)(b * SS + t)) * KVD + n * HDN + d];
    g_vmean[bn * HDN + d] = s * (1.f / SS);
}

// ---------------- compaction -------------------------------------------------
__global__ void scan_kernel() {
    __shared__ int wsum[32];
    int bn = blockIdx.x, t = threadIdx.x;
    int lane = t & 31, w = t >> 5;
    const float* bias = g_bias + bn * SS;
    int f0 = bias[2 * t]     > 0.f;
    int f1 = bias[2 * t + 1] > 0.f;
    int v = f0 + f1;
    int s = v;
    #pragma unroll
    for (int off = 1; off < 32; off <<= 1) {
        int u = __shfl_up_sync(0xffffffffu, s, off);
        if (lane >= off) s += u;
    }
    if (lane == 31) wsum[w] = s;
    __syncthreads();
    if (w == 0) {
        int ws = wsum[lane];
        #pragma unroll
        for (int off = 1; off < 32; off <<= 1) {
            int u = __shfl_up_sync(0xffffffffu, ws, off);
            if (lane >= off) ws += u;
        }
        wsum[lane] = ws;
    }
    __syncthreads();
    int base = (w > 0 ? wsum[w - 1] : 0) + s - v;
    int* pf = g_prefix + bn * (SS + 1);
    if (t == 0) pf[0] = 0;
    pf[2 * t + 1] = base + f0;
    pf[2 * t + 2] = base + f0 + f1;
}

__global__ void gather_kernel() {          // rounds K/V to tf32 on the way
    int bn = blockIdx.y;
    int b = bn >> 2, n = bn & 3;
    int w = threadIdx.x >> 5, lane = threadIdx.x & 31;
    int key = blockIdx.x * 8 + w;
    float bk = g_bias[bn * SS + key];
    if (bk > 0.f) {
        int pos = g_prefix[bn * (SS + 1) + key];
        size_t src = ((size_t)(b * SS + key)) * KVD + n * HDN + lane * 4;
        size_t dst = ((size_t)bn * CAP + pos) * HDN + lane * 4;
        float4 kv = *(const float4*)(g_k + src);
        float4 vv = *(const float4*)(g_v + src);
        kv.x = __uint_as_float(f2tf(kv.x)); kv.y = __uint_as_float(f2tf(kv.y));
        kv.z = __uint_as_float(f2tf(kv.z)); kv.w = __uint_as_float(f2tf(kv.w));
        vv.x = __uint_as_float(f2tf(vv.x)); vv.y = __uint_as_float(f2tf(vv.y));
        vv.z = __uint_as_float(f2tf(vv.z)); vv.w = __uint_as_float(f2tf(vv.w));
        *(float4*)(g_ck + dst) = kv;
        *(float4*)(g_cv + dst) = vv;
        if (lane == 0) { g_cb[bn * CAP + pos] = bk; g_cidx[bn * CAP + pos] = key; }
    }
}

__global__ void pad_kernel() {
    int bn = blockIdx.x;
    int nc = g_prefix[bn * (SS + 1) + SS];
    int r = threadIdx.x >> 5, lane = threadIdx.x & 31;
    int pos = nc + r;
    size_t dst = ((size_t)bn * CAP + pos) * HDN + lane * 4;
    *(float4*)(g_ck + dst) = make_float4(0.f, 0.f, 0.f, 0.f);
    *(float4*)(g_cv + dst) = make_float4(0.f, 0.f, 0.f, 0.f);
    if (lane == 0) { g_cidx[bn * CAP + pos] = 0x7fffffff; g_cb[bn * CAP + pos] = 0.f; }
}

// ---------------- tensor-core flash attention --------------------------------
// CTA: 128 queries (8 warps x m16), key tiles of 32, double-buffered cp.async.
#define QB   128
#define KB   32
#define QSTR 132
#define KSTR 132
#define VSTR 136
#define PSTR 36
#define Q_SH_F   (QB*QSTR)
#define K_SH_F   (KB*KSTR)
#define V_SH_F   (KB*VSTR)
#define P_SH_F   (16*PSTR)
#define ATTN_SMEM ((Q_SH_F + 2*K_SH_F + 2*V_SH_F + 8*P_SH_F + 128)*4)

__global__ __launch_bounds__(256) void attn_mma() {
    extern __shared__ float smem[];
    float* q_sh  = smem;
    float* k_sh  = q_sh + Q_SH_F;
    float* v_sh  = k_sh + 2 * K_SH_F;
    float* p_sh  = v_sh + 2 * V_SH_F;
    float* cb_sh = p_sh + 8 * P_SH_F;      // 2 stages x 32
    int*   idx_sh = (int*)(cb_sh + 64);    // 2 stages x 32

    const int qblk = blockIdx.x;
    const int h    = blockIdx.y;
    const int b    = blockIdx.z;
    const int n    = h >> 2;
    const int bn   = b * HKVN + n;
    const int q0   = qblk * QB;
    const int tid  = threadIdx.x;
    const int w    = tid >> 5;
    const int lane = tid & 31;
    const int lr   = lane >> 2;
    const int lc   = lane & 3;
    const float scale = 0.08838834764831843f;

    // load Q tile: scale + round to tf32
    #pragma unroll
    for (int i = 0; i < 16; i++) {
        int idx = tid + (i << 8);
        int r = idx >> 5, d = (idx & 31) << 2;
        float4 qv = *(const float4*)&g_q[((size_t)(b * SS + q0 + r)) * DD + h * HDN + d];
        qv.x = __uint_as_float(f2tf(qv.x * scale));
        qv.y = __uint_as_float(f2tf(qv.y * scale));
        qv.z = __uint_as_float(f2tf(qv.z * scale));
        qv.w = __uint_as_float(f2tf(qv.w * scale));
        *(float4*)&q_sh[r * QSTR + d] = qv;
    }

    const int limit  = g_prefix[bn * (SS + 1) + q0 + QB];
    const int ntiles = (limit + KB - 1) / KB;

    auto load_tile = [&](int kt, int st) {
        const float* kg = g_ck + ((size_t)bn * CAP + kt * KB) * HDN;
        const float* vg = g_cv + ((size_t)bn * CAP + kt * KB) * HDN;
        float* ks = k_sh + st * K_SH_F;
        float* vs = v_sh + st * V_SH_F;
        #pragma unroll
        for (int p = 0; p < 4; p++) {
            int idx = tid + (p << 8);
            int r = idx >> 5, d = (idx & 31) << 2;
            CP16((uint32_t)__cvta_generic_to_shared(ks + r * KSTR + d), kg + r * HDN + d);
            CP16((uint32_t)__cvta_generic_to_shared(vs + r * VSTR + d), vg + r * HDN + d);
        }
        if (tid < 8)
            CP16((uint32_t)__cvta_generic_to_shared(cb_sh + st * 32 + tid * 4),
                 g_cb + bn * CAP + kt * KB + tid * 4);
        else if (tid < 16)
            CP16((uint32_t)__cvta_generic_to_shared(idx_sh + st * 32 + (tid - 8) * 4),
                 g_cidx + bn * CAP + kt * KB + (tid - 8) * 4);
        asm volatile("cp.async.commit_group;");
    };

    float m0 = -INFINITY, m1 = -INFINITY, l0 = 0.f, l1 = 0.f;
    float oacc[16][4];
    #pragma unroll
    for (int nt = 0; nt < 16; nt++)
        #pragma unroll
        for (int i = 0; i < 4; i++) oacc[nt][i] = 0.f;

    const int qA = q0 + w * 16 + lr;     // row 0; row 1 = qA + 8
    float* pw = p_sh + w * P_SH_F;

    if (ntiles > 0) load_tile(0, 0);

    for (int kt = 0; kt < ntiles; kt++) {
        const int st = kt & 1;
        asm volatile("cp.async.wait_group 0;");
        __syncthreads();
        if (kt + 1 < ntiles) load_tile(kt + 1, st ^ 1);

        const float* ks = k_sh + st * K_SH_F;
        const float* vs = v_sh + st * V_SH_F;
        const float* cb = cb_sh + st * 32;
        const int*   ix = idx_sh + st * 32;

        // ---- scores: Q(16) x K(32), K=128 ----
        float sc[4][4];
        #pragma unroll
        for (int nt = 0; nt < 4; nt++)
            #pragma unroll
            for (int i = 0; i < 4; i++) sc[nt][i] = 0.f;

        #pragma unroll
        for (int kc = 0; kc < 16; kc++) {
            const uint32_t* ap = (const uint32_t*)(q_sh + (w * 16 + lr) * QSTR + kc * 8 + lc);
            uint32_t a[4] = { ap[0], ap[8 * QSTR], ap[4], ap[8 * QSTR + 4] };
            #pragma unroll
            for (int nt = 0; nt < 4; nt++) {
                const uint32_t* bp = (const uint32_t*)(ks + (nt * 8 + lr) * KSTR + kc * 8 + lc);
                uint32_t bb[2] = { bp[0], bp[4] };
                mma_tf32(sc[nt], a, bb);
            }
        }

        // ---- mask + bias -> logits (in place) ----
        #pragma unroll
        for (int nt = 0; nt < 4; nt++) {
            int c0 = nt * 8 + 2 * lc, c1 = c0 + 1;
            float bk0 = cb[c0], bk1 = cb[c1];
            int   i0  = ix[c0], i1  = ix[c1];
            sc[nt][0] = (i0 <= qA)     ? sc[nt][0] + bk0 : -INFINITY;
            sc[nt][1] = (i1 <= qA)     ? sc[nt][1] + bk1 : -INFINITY;
            sc[nt][2] = (i0 <= qA + 8) ? sc[nt][2] + bk0 : -INFINITY;
            sc[nt][3] = (i1 <= qA + 8) ? sc[nt][3] + bk1 : -INFINITY;
        }

        // ---- row max over 32 keys (8 in-lane + 4-lane quad) ----
        float tm0 = -INFINITY, tm1 = -INFINITY;
        #pragma unroll
        for (int nt = 0; nt < 4; nt++) {
            tm0 = fmaxf(tm0, fmaxf(sc[nt][0], sc[nt][1]));
            tm1 = fmaxf(tm1, fmaxf(sc[nt][2], sc[nt][3]));
        }
        tm0 = fmaxf(tm0, __shfl_xor_sync(0xffffffffu, tm0, 1));
        tm0 = fmaxf(tm0, __shfl_xor_sync(0xffffffffu, tm0, 2));
        tm1 = fmaxf(tm1, __shfl_xor_sync(0xffffffffu, tm1, 1));
        tm1 = fmaxf(tm1, __shfl_xor_sync(0xffffffffu, tm1, 2));
        float mn0 = fmaxf(m0, tm0), mn1 = fmaxf(m1, tm1);
        bool act0 = (mn0 > -INFINITY), act1 = (mn1 > -INFINITY);

        // ---- p = exp(logit - mnew), row sums ----
        float rs0 = 0.f, rs1 = 0.f;
        #pragma unroll
        for (int nt = 0; nt < 4; nt++) {
            sc[nt][0] = act0 ? __expf(sc[nt][0] - mn0) : 0.f;
            sc[nt][1] = act0 ? __expf(sc[nt][1] - mn0) : 0.f;
            sc[nt][2] = act1 ? __expf(sc[nt][2] - mn1) : 0.f;
            sc[nt][3] = act1 ? __expf(sc[nt][3] - mn1) : 0.f;
            rs0 += sc[nt][0] + sc[nt][1];
            rs1 += sc[nt][2] + sc[nt][3];
        }
        rs0 += __shfl_xor_sync(0xffffffffu, rs0, 1);
        rs0 += __shfl_xor_sync(0xffffffffu, rs0, 2);
        rs1 += __shfl_xor_sync(0xffffffffu, rs1, 1);
        rs1 += __shfl_xor_sync(0xffffffffu, rs1, 2);

        float corr0 = (act0 && m0 > -INFINITY) ? __expf(m0 - mn0) : (act0 ? 0.f : 1.f);
        float corr1 = (act1 && m1 > -INFINITY) ? __expf(m1 - mn1) : (act1 ? 0.f : 1.f);
        l0 = l0 * corr0 + rs0;  m0 = mn0;
        l1 = l1 * corr1 + rs1;  m1 = mn1;
        #pragma unroll
        for (int nt = 0; nt < 16; nt++) {
            oacc[nt][0] *= corr0; oacc[nt][1] *= corr0;
            oacc[nt][2] *= corr1; oacc[nt][3] *= corr1;
        }

        // ---- P -> smem (tf32), C-layout -> A-layout bounce ----
        #pragma unroll
        for (int nt = 0; nt < 4; nt++) {
            int c0 = nt * 8 + 2 * lc;
            pw[lr * PSTR + c0]           = __uint_as_float(f2tf(sc[nt][0]));
            pw[lr * PSTR + c0 + 1]       = __uint_as_float(f2tf(sc[nt][1]));
            pw[(lr + 8) * PSTR + c0]     = __uint_as_float(f2tf(sc[nt][2]));
            pw[(lr + 8) * PSTR + c0 + 1] = __uint_as_float(f2tf(sc[nt][3]));
        }
        __syncwarp();

        // ---- PV: P(16x32) @ V(32x128) ----
        #pragma unroll
        for (int kc = 0; kc < 4; kc++) {
            const uint32_t* pp = (const uint32_t*)(pw + kc * 8 + lc);
            uint32_t a[4] = { pp[lr * PSTR], pp[(lr + 8) * PSTR],
                              pp[lr * PSTR + 4], pp[(lr + 8) * PSTR + 4] };
            #pragma unroll
            for (int nt = 0; nt < 16; nt++) {
                const uint32_t* bp = (const uint32_t*)(vs + (kc * 8 + lc) * VSTR + nt * 8 + lr);
                uint32_t bb[2] = { bp[0], bp[4 * VSTR] };
                mma_tf32(oacc[nt], a, bb);
            }
        }
        __syncwarp();
    }

    // ---- epilogue ----
    float inv0 = (l0 > 0.f) ? 1.f / l0 : 0.f;
    float inv1 = (l1 > 0.f) ? 1.f / l1 : 0.f;
    size_t row0 = (size_t)(b * SS + qA) * DD + h * HDN;
    size_t row1 = row0 + (size_t)8 * DD;
    #pragma unroll
    for (int nt = 0; nt < 16; nt++) {
        int col = nt * 8 + 2 * lc;
        float2 r0, r1;
        if (l0 > 0.f) r0 = make_float2(oacc[nt][0] * inv0, oacc[nt][1] * inv0);
        else          r0 = make_float2(g_vmean[bn * HDN + col], g_vmean[bn * HDN + col + 1]);
        if (l1 > 0.f) r1 = make_float2(oacc[nt][2] * inv1, oacc[nt][3] * inv1);
        else          r1 = make_float2(g_vmean[bn * HDN + col], g_vmean[bn * HDN + col + 1]);
        r0.x = __uint_as_float(f2tf(r0.x)); r0.y = __uint_as_float(f2tf(r0.y));
        r1.x = __uint_as_float(f2tf(r1.x)); r1.y = __uint_as_float(f2tf(r1.y));
        *(float2*)&g_o[row0 + col] = r0;
        *(float2*)&g_o[row1 + col] = r1;
    }
}

// ---------------- launch -----------------------------------------------------
extern "C" void kernel_launch(void* const* d_in, const int* in_sizes, int n_in,
                              void* d_out, int out_size) {
    const float* X  = (const float*)d_in[0];
    const float* Wq = (const float*)d_in[1];
    const float* Wk = (const float*)d_in[2];
    const float* Wv = (const float*)d_in[3];
    const float* Wg = (const float*)d_in[4];
    const float* Wd = (const float*)d_in[5];
    const float* Wo = (const float*)d_in[6];
    float* out = (float*)d_out;

    float *qp, *kp, *vp, *op, *xr, *wqr, *wkr, *wvr, *wor, *wqg, *wvd;
    cudaGetSymbolAddress((void**)&qp, g_q);
    cudaGetSymbolAddress((void**)&kp, g_k);
    cudaGetSymbolAddress((void**)&vp, g_v);
    cudaGetSymbolAddress((void**)&op, g_o);
    cudaGetSymbolAddress((void**)&xr, g_xr);
    cudaGetSymbolAddress((void**)&wqr, g_wqr);
    cudaGetSymbolAddress((void**)&wkr, g_wkr);
    cudaGetSymbolAddress((void**)&wvr, g_wvr);
    cudaGetSymbolAddress((void**)&wor, g_wor);
    cudaGetSymbolAddress((void**)&wqg, g_wqg);
    cudaGetSymbolAddress((void**)&wvd, g_wvd);

    cudaFuncSetAttribute(gemm_tf32, cudaFuncAttributeMaxDynamicSharedMemorySize, GEMM_SMEM);
    cudaFuncSetAttribute(attn_mma, cudaFuncAttributeMaxDynamicSharedMemorySize, ATTN_SMEM);

    round_tf32<<<(MROWS*DD/4 + 255)/256, 256>>>(X,  xr,  MROWS*DD/4);
    round_tf32<<<(DD*DD/4    + 255)/256, 256>>>(Wq, wqr, DD*DD/4);
    round_tf32<<<(DD*KVD/4   + 255)/256, 256>>>(Wk, wkr, DD*KVD/4);
    round_tf32<<<(DD*KVD/4   + 255)/256, 256>>>(Wv, wvr, DD*KVD/4);
    round_tf32<<<(DD*DD/4    + 255)/256, 256>>>(Wo, wor, DD*DD/4);

    fuse_w<<<(DD*32 + 255)/256, 256>>>(Wq, Wg, wqg, DD);
    fuse_w<<<(DD*32 + 255)/256, 256>>>(Wv, Wd, wvd, KVD);

    bias2_kernel<<<(MROWS*32 + 255)/256, 256>>>(X);

    gemm_tf32<<<dim3(DD / 128, MROWS / 128), 256, GEMM_SMEM>>>(xr, wqr, qp, MROWS, DD,  DD);
    gemm_tf32<<<dim3(KVD / 128, MROWS / 128), 256, GEMM_SMEM>>>(xr, wkr, kp, MROWS, KVD, DD);
    gemm_tf32<<<dim3(KVD / 128, MROWS / 128), 256, GEMM_SMEM>>>(xr, wvr, vp, MROWS, KVD, DD);

    vmean_kernel<<<BB * HKVN, HDN>>>();

    scan_kernel<<<BB * HKVN, 1024>>>();
    gather_kernel<<<dim3(SS / 8, BB * HKVN), 256>>>();
    pad_kernel<<<BB * HKVN, 1024>>>();

    attn_mma<<<dim3(SS / QB, HH, BB), 256, ATTN_SMEM>>>();

    gemm_tf32<<<dim3(DD / 128, MROWS / 128), 256, GEMM_SMEM>>>(op, wor, out, MROWS, DD, DD);
}

// round 8
// speedup vs baseline: 5.1181x; 1.1484x over previous
#include <cuda_runtime.h>
#include <math.h>
#include <stdint.h>

#define BB   2
#define SS   2048
#define DD   2048
#define HH   16
#define HKVN 4
#define HDN  128
#define MROWS (BB*SS)
#define NQKV 3072            // Q(2048) | K(512) | V(512)
#define CAP  (SS+32)

// ---------------- scratch ----------------------------------------------------
__device__ float g_qkv[MROWS*NQKV];      // fused projections [4096][3072]
__device__ float g_bias[BB*HKVN*SS];
__device__ float g_vmean[BB*HKVN*HDN];
__device__ float g_vpart[8*8*HDN];
__device__ float g_o[MROWS*DD];
__device__ float g_xr[MROWS*DD];         // tf32-rounded X
__device__ float g_wb[DD*NQKV];          // rounded [Wq|Wk|Wv]  [2048][3072]
__device__ float g_wor[DD*DD];           // rounded Wo [2048][2048]
__device__ float g_wqg[DD*HKVN];
__device__ float g_wvd[DD*HKVN];
__device__ float g_ck[BB*HKVN*CAP*HDN];
__device__ float g_cv[BB*HKVN*CAP*HDN];
__device__ float g_cb[BB*HKVN*CAP];
__device__ int   g_cidx[BB*HKVN*CAP];
__device__ int   g_prefix[BB*HKVN*(SS+1)];

__device__ __forceinline__ uint32_t f2tf(float f) {
    uint32_t u;
    asm("cvt.rna.tf32.f32 %0, %1;" : "=r"(u) : "f"(f));
    return u;
}
__device__ __forceinline__ float f2tff(float f) { return __uint_as_float(f2tf(f)); }

__device__ __forceinline__ void mma_tf32(float* c, const uint32_t* a, const uint32_t* b) {
    asm volatile(
        "mma.sync.aligned.m16n8k8.row.col.f32.tf32.tf32.f32 "
        "{%0,%1,%2,%3},{%4,%5,%6,%7},{%8,%9},{%0,%1,%2,%3};"
        : "+f"(c[0]), "+f"(c[1]), "+f"(c[2]), "+f"(c[3])
        : "r"(a[0]), "r"(a[1]), "r"(a[2]), "r"(a[3]), "r"(b[0]), "r"(b[1]));
}
#define CP16(dst, src) asm volatile("cp.async.cg.shared.global [%0], [%1], 16;" :: "r"(dst), "l"(src))

// ---------------- fuse: out[d][n] = sum_j A[d][j]*B[j][n] (fp32) ------------
__global__ void fuse_w(const float* __restrict__ A, const float* __restrict__ B,
                       float* __restrict__ out, int K) {
    int d    = (blockIdx.x * blockDim.x + threadIdx.x) >> 5;
    int lane = threadIdx.x & 31;
    if (d >= DD) return;
    float a0 = 0.f, a1 = 0.f, a2 = 0.f, a3 = 0.f;
    const float* ar = A + (size_t)d * K;
    for (int j = lane; j < K; j += 32) {
        float a = ar[j];
        float4 b = *(const float4*)&B[j * 4];
        a0 += a * b.x; a1 += a * b.y; a2 += a * b.z; a3 += a * b.w;
    }
    #pragma unroll
    for (int off = 16; off; off >>= 1) {
        a0 += __shfl_xor_sync(0xffffffffu, a0, off);
        a1 += __shfl_xor_sync(0xffffffffu, a1, off);
        a2 += __shfl_xor_sync(0xffffffffu, a2, off);
        a3 += __shfl_xor_sync(0xffffffffu, a3, off);
    }
    if (lane == 0) { *(float4*)&out[d * 4] = make_float4(a0, a1, a2, a3); }
}

// ---------------- prep X: tf32 round + exact fp32 bias ----------------------
__global__ void prep_x(const float* __restrict__ X) {
    __shared__ float red[8][8];
    const int row = blockIdx.x, tid = threadIdx.x;
    const int lane = tid & 31, w = tid >> 5;
    const float* xrow = X + (size_t)row * DD;
    float4 v0 = *(const float4*)(xrow + tid * 8);
    float4 v1 = *(const float4*)(xrow + tid * 8 + 4);
    float xs[8] = {v0.x, v0.y, v0.z, v0.w, v1.x, v1.y, v1.z, v1.w};
    float sg[4] = {0,0,0,0}, sd[4] = {0,0,0,0};
    #pragma unroll
    for (int j = 0; j < 8; j++) {
        int d = tid * 8 + j;
        float4 wg = *(const float4*)&g_wqg[d * 4];
        float4 wv = *(const float4*)&g_wvd[d * 4];
        sg[0] += xs[j]*wg.x; sg[1] += xs[j]*wg.y; sg[2] += xs[j]*wg.z; sg[3] += xs[j]*wg.w;
        sd[0] += xs[j]*wv.x; sd[1] += xs[j]*wv.y; sd[2] += xs[j]*wv.z; sd[3] += xs[j]*wv.w;
    }
    *(float4*)&g_xr[(size_t)row * DD + tid * 8] =
        make_float4(f2tff(v0.x), f2tff(v0.y), f2tff(v0.z), f2tff(v0.w));
    *(float4*)&g_xr[(size_t)row * DD + tid * 8 + 4] =
        make_float4(f2tff(v1.x), f2tff(v1.y), f2tff(v1.z), f2tff(v1.w));
    #pragma unroll
    for (int off = 16; off; off >>= 1)
        #pragma unroll
        for (int n = 0; n < 4; n++) {
            sg[n] += __shfl_xor_sync(0xffffffffu, sg[n], off);
            sd[n] += __shfl_xor_sync(0xffffffffu, sd[n], off);
        }
    if (lane == 0) {
        red[w][0] = sg[0]; red[w][1] = sg[1]; red[w][2] = sg[2]; red[w][3] = sg[3];
        red[w][4] = sd[0]; red[w][5] = sd[1]; red[w][6] = sd[2]; red[w][7] = sd[3];
    }
    __syncthreads();
    if (tid < 8) {
        float a = 0.f;
        #pragma unroll
        for (int ww = 0; ww < 8; ww++) a += red[ww][tid];
        red[0][tid] = a;
    }
    __syncthreads();
    if (tid < 4) {
        int b = row / SS, s = row % SS;
        g_bias[(b * HKVN + tid) * SS + s] = red[0][tid + 4] / (1.f + expf(-red[0][tid]));
    }
}

// ---------------- build combined rounded weights [2048][3072] ---------------
__global__ void round_wb(const float* __restrict__ Wq, const float* __restrict__ Wk,
                         const float* __restrict__ Wv) {
    int i = blockIdx.x * blockDim.x + threadIdx.x;   // float4 index
    if (i >= DD * NQKV / 4) return;
    int j = (i % (NQKV / 4)) * 4;
    int k = i / (NQKV / 4);
    const float* src;
    if (j < 2048)      src = Wq + (size_t)k * 2048 + j;
    else if (j < 2560) src = Wk + (size_t)k * 512 + (j - 2048);
    else               src = Wv + (size_t)k * 512 + (j - 2560);
    float4 v = *(const float4*)src;
    v.x = f2tff(v.x); v.y = f2tff(v.y); v.z = f2tff(v.z); v.w = f2tff(v.w);
    *(float4*)&g_wb[(size_t)k * NQKV + j] = v;
}

__global__ void round_tf32(const float* __restrict__ in, float* __restrict__ out, int n4) {
    int i = blockIdx.x * blockDim.x + threadIdx.x;
    if (i < n4) {
        float4 v = ((const float4*)in)[i];
        v.x = f2tff(v.x); v.y = f2tff(v.y); v.z = f2tff(v.z); v.w = f2tff(v.w);
        ((float4*)out)[i] = v;
    }
}

// ---------------- tf32 GEMM (pre-rounded operands) --------------------------
#define ASTR 36
#define BSTR 136
#define A_TILE (128*ASTR)
#define B_TILE (32*BSTR)
#define GEMM_SMEM ((2*A_TILE + 2*B_TILE)*4)

__global__ __launch_bounds__(256, 2) void gemm_tf32(const float* __restrict__ A,
                                                    const float* __restrict__ B,
                                                    float* __restrict__ C,
                                                    int M, int N, int K) {
    extern __shared__ float sm[];
    float* As = sm;
    float* Bs = sm + 2 * A_TILE;

    const int tid  = threadIdx.x;
    const int wid  = tid >> 5;
    const int lane = tid & 31;
    const int wm   = (wid & 3) << 5;
    const int wn   = (wid >> 2) << 6;
    const int m0   = blockIdx.y << 7;
    const int n0   = blockIdx.x << 7;
    const int lr   = lane >> 2;
    const int lc   = lane & 3;

    float acc[2][8][4];
    #pragma unroll
    for (int mt = 0; mt < 2; mt++)
        #pragma unroll
        for (int nt = 0; nt < 8; nt++)
            #pragma unroll
            for (int i = 0; i < 4; i++) acc[mt][nt][i] = 0.f;

    const int KT = K >> 5;

    auto load_stage = [&](int kt, int s) {
        float* as = As + s * A_TILE;
        float* bs = Bs + s * B_TILE;
        #pragma unroll
        for (int p = 0; p < 4; p++) {
            int idx = tid + (p << 8);
            int r = idx >> 3, kv = (idx & 7) << 2;
            uint32_t dst = (uint32_t)__cvta_generic_to_shared(as + r * ASTR + kv);
            CP16(dst, A + (size_t)(m0 + r) * K + (kt << 5) + kv);
        }
        #pragma unroll
        for (int p = 0; p < 4; p++) {
            int idx = tid + (p << 8);
            int r = idx >> 5, nv = (idx & 31) << 2;
            uint32_t dst = (uint32_t)__cvta_generic_to_shared(bs + r * BSTR + nv);
            CP16(dst, B + (size_t)((kt << 5) + r) * N + n0 + nv);
        }
        asm volatile("cp.async.commit_group;");
    };

    load_stage(0, 0);

    for (int kt = 0; kt < KT; kt++) {
        asm volatile("cp.async.wait_group 0;");
        __syncthreads();
        if (kt + 1 < KT) load_stage(kt + 1, (kt + 1) & 1);

        const float* as = As + (kt & 1) * A_TILE;
        const float* bs = Bs + (kt & 1) * B_TILE;

        #pragma unroll
        for (int ks = 0; ks < 4; ks++) {
            const int kk = ks << 3;
            uint32_t afr[2][4];
            #pragma unroll
            for (int mt = 0; mt < 2; mt++) {
                const uint32_t* ap = (const uint32_t*)(as + (wm + (mt << 4) + lr) * ASTR + kk + lc);
                afr[mt][0] = ap[0];
                afr[mt][1] = ap[8 * ASTR];
                afr[mt][2] = ap[4];
                afr[mt][3] = ap[8 * ASTR + 4];
            }
            #pragma unroll
            for (int nt = 0; nt < 8; nt++) {
                const uint32_t* bp = (const uint32_t*)(bs + (kk + lc) * BSTR + wn + (nt << 3) + lr);
                uint32_t bfr[2];
                bfr[0] = bp[0];
                bfr[1] = bp[4 * BSTR];
                mma_tf32(acc[0][nt], afr[0], bfr);
                mma_tf32(acc[1][nt], afr[1], bfr);
            }
        }
        // single barrier per iteration (top-of-loop) is sufficient for
        // double buffering: next overwrite happens only after all warps
        // pass the next top barrier.
    }

    #pragma unroll
    for (int mt = 0; mt < 2; mt++) {
        #pragma unroll
        for (int nt = 0; nt < 8; nt++) {
            int row = m0 + wm + (mt << 4) + lr;
            int col = n0 + wn + (nt << 3) + (lc << 1);
            *(float2*)&C[(size_t)row * N + col] =
                make_float2(acc[mt][nt][0], acc[mt][nt][1]);
            *(float2*)&C[(size_t)(row + 8) * N + col] =
                make_float2(acc[mt][nt][2], acc[mt][nt][3]);
        }
    }
}

// ---------------- vmean (two-phase) ------------------------------------------
__global__ void vmean_part() {   // grid (8 chunks, 8 bn), block 128
    int ch = blockIdx.x, bn = blockIdx.y, d = threadIdx.x;
    int b = bn >> 2, n = bn & 3;
    float s = 0.f;
    int r0 = ch * 256;
    #pragma unroll 4
    for (int t = 0; t < 256; t++)
        s += g_qkv[(size_t)(b * SS + r0 + t) * NQKV + 2560 + n * HDN + d];
    g_vpart[(bn * 8 + ch) * HDN + d] = s;
}
__global__ void vmean_fin() {
    int bn = blockIdx.x, d = threadIdx.x;
    float s = 0.f;
    #pragma unroll
    for (int ch = 0; ch < 8; ch++) s += g_vpart[(bn * 8 + ch) * HDN + d];
    g_vmean[bn * HDN + d] = s * (1.f / SS);
}

// ---------------- compaction -------------------------------------------------
__global__ void scan_kernel() {
    __shared__ int wsum[32];
    int bn = blockIdx.x, t = threadIdx.x;
    int lane = t & 31, w = t >> 5;
    const float* bias = g_bias + bn * SS;
    int f0 = bias[2 * t]     > 0.f;
    int f1 = bias[2 * t + 1] > 0.f;
    int v = f0 + f1;
    int s = v;
    #pragma unroll
    for (int off = 1; off < 32; off <<= 1) {
        int u = __shfl_up_sync(0xffffffffu, s, off);
        if (lane >= off) s += u;
    }
    if (lane == 31) wsum[w] = s;
    __syncthreads();
    if (w == 0) {
        int ws = wsum[lane];
        #pragma unroll
        for (int off = 1; off < 32; off <<= 1) {
            int u = __shfl_up_sync(0xffffffffu, ws, off);
            if (lane >= off) ws += u;
        }
        wsum[lane] = ws;
    }
    __syncthreads();
    int base = (w > 0 ? wsum[w - 1] : 0) + s - v;
    int* pf = g_prefix + bn * (SS + 1);
    if (t == 0) pf[0] = 0;
    pf[2 * t + 1] = base + f0;
    pf[2 * t + 2] = base + f0 + f1;
}

__global__ void gather_kernel() {
    int bn = blockIdx.y;
    int b = bn >> 2, n = bn & 3;
    int w = threadIdx.x >> 5, lane = threadIdx.x & 31;
    int key = blockIdx.x * 8 + w;
    float bk = g_bias[bn * SS + key];
    if (bk > 0.f) {
        int pos = g_prefix[bn * (SS + 1) + key];
        size_t src = (size_t)(b * SS + key) * NQKV + 2048 + n * HDN + lane * 4;
        size_t dst = ((size_t)bn * CAP + pos) * HDN + lane * 4;
        float4 kv = *(const float4*)(g_qkv + src);
        float4 vv = *(const float4*)(g_qkv + src + 512);
        kv.x = f2tff(kv.x); kv.y = f2tff(kv.y); kv.z = f2tff(kv.z); kv.w = f2tff(kv.w);
        vv.x = f2tff(vv.x); vv.y = f2tff(vv.y); vv.z = f2tff(vv.z); vv.w = f2tff(vv.w);
        *(float4*)(g_ck + dst) = kv;
        *(float4*)(g_cv + dst) = vv;
        if (lane == 0) { g_cb[bn * CAP + pos] = bk; g_cidx[bn * CAP + pos] = key; }
    }
}

__global__ void pad_kernel() {
    int bn = blockIdx.x;
    int nc = g_prefix[bn * (SS + 1) + SS];
    int r = threadIdx.x >> 5, lane = threadIdx.x & 31;
    int pos = nc + r;
    size_t dst = ((size_t)bn * CAP + pos) * HDN + lane * 4;
    *(float4*)(g_ck + dst) = make_float4(0.f, 0.f, 0.f, 0.f);
    *(float4*)(g_cv + dst) = make_float4(0.f, 0.f, 0.f, 0.f);
    if (lane == 0) { g_cidx[bn * CAP + pos] = 0x7fffffff; g_cb[bn * CAP + pos] = 0.f; }
}

// ---------------- tensor-core flash attention --------------------------------
#define QB   128
#define KB   32
#define QSTR 132
#define KSTR 132
#define VSTR 136
#define PSTR 36
#define Q_SH_F   (QB*QSTR)
#define K_SH_F   (KB*KSTR)
#define V_SH_F   (KB*VSTR)
#define P_SH_F   (16*PSTR)
#define ATTN_SMEM ((Q_SH_F + 2*K_SH_F + 2*V_SH_F + 8*P_SH_F + 128)*4)

__global__ __launch_bounds__(256) void attn_mma() {
    extern __shared__ float smem[];
    float* q_sh  = smem;
    float* k_sh  = q_sh + Q_SH_F;
    float* v_sh  = k_sh + 2 * K_SH_F;
    float* p_sh  = v_sh + 2 * V_SH_F;
    float* cb_sh = p_sh + 8 * P_SH_F;
    int*   idx_sh = (int*)(cb_sh + 64);

    const int qblk = (gridDim.x - 1) - blockIdx.x;   // heavy blocks first
    const int h    = blockIdx.y;
    const int b    = blockIdx.z;
    const int n    = h >> 2;
    const int bn   = b * HKVN + n;
    const int q0   = qblk * QB;
    const int tid  = threadIdx.x;
    const int w    = tid >> 5;
    const int lane = tid & 31;
    const int lr   = lane >> 2;
    const int lc   = lane & 3;
    const float scale = 0.08838834764831843f;

    #pragma unroll
    for (int i = 0; i < 16; i++) {
        int idx = tid + (i << 8);
        int r = idx >> 5, d = (idx & 31) << 2;
        float4 qv = *(const float4*)&g_qkv[((size_t)(b * SS + q0 + r)) * NQKV + h * HDN + d];
        qv.x = f2tff(qv.x * scale); qv.y = f2tff(qv.y * scale);
        qv.z = f2tff(qv.z * scale); qv.w = f2tff(qv.w * scale);
        *(float4*)&q_sh[r * QSTR + d] = qv;
    }

    const int limit  = g_prefix[bn * (SS + 1) + q0 + QB];
    const int ntiles = (limit + KB - 1) / KB;

    auto load_tile = [&](int kt, int st) {
        const float* kg = g_ck + ((size_t)bn * CAP + kt * KB) * HDN;
        const float* vg = g_cv + ((size_t)bn * CAP + kt * KB) * HDN;
        float* ks = k_sh + st * K_SH_F;
        float* vs = v_sh + st * V_SH_F;
        #pragma unroll
        for (int p = 0; p < 4; p++) {
            int idx = tid + (p << 8);
            int r = idx >> 5, d = (idx & 31) << 2;
            CP16((uint32_t)__cvta_generic_to_shared(ks + r * KSTR + d), kg + r * HDN + d);
            CP16((uint32_t)__cvta_generic_to_shared(vs + r * VSTR + d), vg + r * HDN + d);
        }
        if (tid < 8)
            CP16((uint32_t)__cvta_generic_to_shared(cb_sh + st * 32 + tid * 4),
                 g_cb + bn * CAP + kt * KB + tid * 4);
        else if (tid < 16)
            CP16((uint32_t)__cvta_generic_to_shared(idx_sh + st * 32 + (tid - 8) * 4),
                 g_cidx + bn * CAP + kt * KB + (tid - 8) * 4);
        asm volatile("cp.async.commit_group;");
    };

    float m0 = -INFINITY, m1 = -INFINITY, l0 = 0.f, l1 = 0.f;
    float oacc[16][4];
    #pragma unroll
    for (int nt = 0; nt < 16; nt++)
        #pragma unroll
        for (int i = 0; i < 4; i++) oacc[nt][i] = 0.f;

    const int qA = q0 + w * 16 + lr;
    float* pw = p_sh + w * P_SH_F;

    if (ntiles > 0) load_tile(0, 0);

    for (int kt = 0; kt < ntiles; kt++) {
        const int st = kt & 1;
        asm volatile("cp.async.wait_group 0;");
        __syncthreads();
        if (kt + 1 < ntiles) load_tile(kt + 1, st ^ 1);

        const float* ks = k_sh + st * K_SH_F;
        const float* vs = v_sh + st * V_SH_F;
        const float* cb = cb_sh + st * 32;
        const int*   ix = idx_sh + st * 32;

        float sc[4][4];
        #pragma unroll
        for (int nt = 0; nt < 4; nt++)
            #pragma unroll
            for (int i = 0; i < 4; i++) sc[nt][i] = 0.f;

        #pragma unroll
        for (int kc = 0; kc < 16; kc++) {
            const uint32_t* ap = (const uint32_t*)(q_sh + (w * 16 + lr) * QSTR + kc * 8 + lc);
            uint32_t a[4] = { ap[0], ap[8 * QSTR], ap[4], ap[8 * QSTR + 4] };
            #pragma unroll
            for (int nt = 0; nt < 4; nt++) {
                const uint32_t* bp = (const uint32_t*)(ks + (nt * 8 + lr) * KSTR + kc * 8 + lc);
                uint32_t bb[2] = { bp[0], bp[4] };
                mma_tf32(sc[nt], a, bb);
            }
        }

        #pragma unroll
        for (int nt = 0; nt < 4; nt++) {
            int c0 = nt * 8 + 2 * lc, c1 = c0 + 1;
            float bk0 = cb[c0], bk1 = cb[c1];
            int   i0  = ix[c0], i1  = ix[c1];
            sc[nt][0] = (i0 <= qA)     ? sc[nt][0] + bk0 : -INFINITY;
            sc[nt][1] = (i1 <= qA)     ? sc[nt][1] + bk1 : -INFINITY;
            sc[nt][2] = (i0 <= qA + 8) ? sc[nt][2] + bk0 : -INFINITY;
            sc[nt][3] = (i1 <= qA + 8) ? sc[nt][3] + bk1 : -INFINITY;
        }

        float tm0 = -INFINITY, tm1 = -INFINITY;
        #pragma unroll
        for (int nt = 0; nt < 4; nt++) {
            tm0 = fmaxf(tm0, fmaxf(sc[nt][0], sc[nt][1]));
            tm1 = fmaxf(tm1, fmaxf(sc[nt][2], sc[nt][3]));
        }
        tm0 = fmaxf(tm0, __shfl_xor_sync(0xffffffffu, tm0, 1));
        tm0 = fmaxf(tm0, __shfl_xor_sync(0xffffffffu, tm0, 2));
        tm1 = fmaxf(tm1, __shfl_xor_sync(0xffffffffu, tm1, 1));
        tm1 = fmaxf(tm1, __shfl_xor_sync(0xffffffffu, tm1, 2));
        float mn0 = fmaxf(m0, tm0), mn1 = fmaxf(m1, tm1);
        bool act0 = (mn0 > -INFINITY), act1 = (mn1 > -INFINITY);

        float rs0 = 0.f, rs1 = 0.f;
        #pragma unroll
        for (int nt = 0; nt < 4; nt++) {
            sc[nt][0] = act0 ? __expf(sc[nt][0] - mn0) : 0.f;
            sc[nt][1] = act0 ? __expf(sc[nt][1] - mn0) : 0.f;
            sc[nt][2] = act1 ? __expf(sc[nt][2] - mn1) : 0.f;
            sc[nt][3] = act1 ? __expf(sc[nt][3] - mn1) : 0.f;
            rs0 += sc[nt][0] + sc[nt][1];
            rs1 += sc[nt][2] + sc[nt][3];
        }
        rs0 += __shfl_xor_sync(0xffffffffu, rs0, 1);
        rs0 += __shfl_xor_sync(0xffffffffu, rs0, 2);
        rs1 += __shfl_xor_sync(0xffffffffu, rs1, 1);
        rs1 += __shfl_xor_sync(0xffffffffu, rs1, 2);

        float corr0 = (act0 && m0 > -INFINITY) ? __expf(m0 - mn0) : (act0 ? 0.f : 1.f);
        float corr1 = (act1 && m1 > -INFINITY) ? __expf(m1 - mn1) : (act1 ? 0.f : 1.f);
        l0 = l0 * corr0 + rs0;  m0 = mn0;
        l1 = l1 * corr1 + rs1;  m1 = mn1;
        #pragma unroll
        for (int nt = 0; nt < 16; nt++) {
            oacc[nt][0] *= corr0; oacc[nt][1] *= corr0;
            oacc[nt][2] *= corr1; oacc[nt][3] *= corr1;
        }

        #pragma unroll
        for (int nt = 0; nt < 4; nt++) {
            int c0 = nt * 8 + 2 * lc;
            pw[lr * PSTR + c0]           = f2tff(sc[nt][0]);
            pw[lr * PSTR + c0 + 1]       = f2tff(sc[nt][1]);
            pw[(lr + 8) * PSTR + c0]     = f2tff(sc[nt][2]);
            pw[(lr + 8) * PSTR + c0 + 1] = f2tff(sc[nt][3]);
        }
        __syncwarp();

        #pragma unroll
        for (int kc = 0; kc < 4; kc++) {
            const uint32_t* pp = (const uint32_t*)(pw + kc * 8 + lc);
            uint32_t a[4] = { pp[lr * PSTR], pp[(lr + 8) * PSTR],
                              pp[lr * PSTR + 4], pp[(lr + 8) * PSTR + 4] };
            #pragma unroll
            for (int nt = 0; nt < 16; nt++) {
                const uint32_t* bp = (const uint32_t*)(vs + (kc * 8 + lc) * VSTR + nt * 8 + lr);
                uint32_t bb[2] = { bp[0], bp[4 * VSTR] };
                mma_tf32(oacc[nt], a, bb);
            }
        }
        __syncwarp();
    }

    float inv0 = (l0 > 0.f) ? 1.f / l0 : 0.f;
    float inv1 = (l1 > 0.f) ? 1.f / l1 : 0.f;
    size_t row0 = (size_t)(b * SS + qA) * DD + h * HDN;
    size_t row1 = row0 + (size_t)8 * DD;
    #pragma unroll
    for (int nt = 0; nt < 16; nt++) {
        int col = nt * 8 + 2 * lc;
        float2 r0, r1;
        if (l0 > 0.f) r0 = make_float2(oacc[nt][0] * inv0, oacc[nt][1] * inv0);
        else          r0 = make_float2(g_vmean[bn * HDN + col], g_vmean[bn * HDN + col + 1]);
        if (l1 > 0.f) r1 = make_float2(oacc[nt][2] * inv1, oacc[nt][3] * inv1);
        else          r1 = make_float2(g_vmean[bn * HDN + col], g_vmean[bn * HDN + col + 1]);
        r0.x = f2tff(r0.x); r0.y = f2tff(r0.y);
        r1.x = f2tff(r1.x); r1.y = f2tff(r1.y);
        *(float2*)&g_o[row0 + col] = r0;
        *(float2*)&g_o[row1 + col] = r1;
    }
}

// ---------------- launch -----------------------------------------------------
extern "C" void kernel_launch(void* const* d_in, const int* in_sizes, int n_in,
                              void* d_out, int out_size) {
    const float* X  = (const float*)d_in[0];
    const float* Wq = (const float*)d_in[1];
    const float* Wk = (const float*)d_in[2];
    const float* Wv = (const float*)d_in[3];
    const float* Wg = (const float*)d_in[4];
    const float* Wd = (const float*)d_in[5];
    const float* Wo = (const float*)d_in[6];
    float* out = (float*)d_out;

    float *qkvp, *op, *xr, *wb, *wor, *wqg, *wvd;
    cudaGetSymbolAddress((void**)&qkvp, g_qkv);
    cudaGetSymbolAddress((void**)&op,   g_o);
    cudaGetSymbolAddress((void**)&xr,   g_xr);
    cudaGetSymbolAddress((void**)&wb,   g_wb);
    cudaGetSymbolAddress((void**)&wor,  g_wor);
    cudaGetSymbolAddress((void**)&wqg,  g_wqg);
    cudaGetSymbolAddress((void**)&wvd,  g_wvd);

    cudaFuncSetAttribute(gemm_tf32, cudaFuncAttributeMaxDynamicSharedMemorySize, GEMM_SMEM);
    cudaFuncSetAttribute(attn_mma, cudaFuncAttributeMaxDynamicSharedMemorySize, ATTN_SMEM);

    // launches 0-4 (prep), launch 5 = big QKV GEMM (profiled by ncu -s 5)
    fuse_w<<<(DD * 32 + 255) / 256, 256>>>(Wq, Wg, wqg, DD);                 // 0
    fuse_w<<<(DD * 32 + 255) / 256, 256>>>(Wv, Wd, wvd, HKVN * HDN);        // 1
    prep_x<<<MROWS, 256>>>(X);                                               // 2
    round_wb<<<(DD * NQKV / 4 + 255) / 256, 256>>>(Wq, Wk, Wv);             // 3
    round_tf32<<<(DD * DD / 4 + 255) / 256, 256>>>(Wo, wor, DD * DD / 4);   // 4

    gemm_tf32<<<dim3(NQKV / 128, MROWS / 128), 256, GEMM_SMEM>>>(            // 5
        xr, wb, qkvp, MROWS, NQKV, DD);

    vmean_part<<<dim3(8, BB * HKVN), HDN>>>();
    vmean_fin<<<BB * HKVN, HDN>>>();

    scan_kernel<<<BB * HKVN, 1024>>>();
    gather_kernel<<<dim3(SS / 8, BB * HKVN), 256>>>();
    pad_kernel<<<BB * HKVN, 1024>>>();

    attn_mma<<<dim3(SS / QB, HH, BB), 256, ATTN_SMEM>>>();

    gemm_tf32<<<dim3(DD / 128, MROWS / 128), 256, GEMM_SMEM>>>(op, wor, out, MROWS, DD, DD);
}